// round 1
// baseline (speedup 1.0000x reference)
#include <cuda_runtime.h>
#include <cstdint>

#define HH 200
#define WW 272
#define NPIX 54400
#define NANCH 489600
#define PRE_NMS 6000
#define NWORDS 188          // ceil(6016/32)
#define NBOX_PAD 6016
#define POST_NMS 1000
#define CAND_CAP 8192

// ---------------- scratch (device globals; no allocation anywhere) ----------
__device__ float        g_x[256 * NPIX];          // conv1 output (relu), [oc][p]
__device__ float        g_wt[2304 * 256];         // transposed w1: [(ic*9+k)][oc]
__device__ unsigned     g_key[NANCH];             // sortable score keys
__device__ float4       g_off4[NANCH];            // reg deltas per anchor
__device__ int          g_hist[65536];
__device__ int          g_hist2[65536];
__device__ int          g_B, g_need;
__device__ unsigned     g_T;
__device__ int          g_cnt;
__device__ unsigned long long g_cand[CAND_CAP];
__device__ int          g_sel[PRE_NMS];
__device__ float4       g_props[NBOX_PAD];
__device__ int          g_valid[PRE_NMS];
__device__ unsigned     g_mask[PRE_NMS * NWORDS];
__device__ int          g_keep[PRE_NMS];

__device__ __constant__ float c_aw[9] = {
    45.254833995939045f, 32.f, 22.627416997969522f,
    90.50966799187809f,  64.f, 45.254833995939045f,
    181.01933598375618f, 128.f, 90.50966799187809f};
__device__ __constant__ float c_ah[9] = {
    22.627416997969522f, 32.f, 45.254833995939045f,
    45.254833995939045f, 64.f, 90.50966799187809f,
    90.50966799187809f,  128.f, 181.01933598375618f};

__device__ __forceinline__ unsigned fkey(float f) {
    unsigned u = __float_as_uint(f);
    return (u & 0x80000000u) ? ~u : (u | 0x80000000u);
}

// ---------------- 0: zero scratch + output ----------------------------------
__global__ void zero_k(float* out) {
    int i = blockIdx.x * 256 + threadIdx.x;
    if (i < 65536) { g_hist[i] = 0; g_hist2[i] = 0; }
    if (i == 0) g_cnt = 0;
    if (i < POST_NMS * 4) out[i] = 0.f;
}

// ---------------- 1: transpose conv1 weights --------------------------------
__global__ void transw_k(const float* __restrict__ w1) {
    int i = blockIdx.x * 256 + threadIdx.x;
    if (i < 256 * 2304) {
        int oc = i / 2304, r = i % 2304;
        g_wt[r * 256 + oc] = w1[i];
    }
}

// ---------------- 2: 3x3 conv 256->256 + bias + relu ------------------------
// grid (5, 200, 2), block 256. Tile: 128 oc x 64 px (one row segment).
__global__ void __launch_bounds__(256) conv3x3_k(const float* __restrict__ f,
                                                 const float* __restrict__ b1) {
    __shared__ __align__(16) float sx[8][3][68];     // 8 ic x 3 rows x 66(+pad)
    __shared__ __align__(16) float sw[8][9][128];    // 8 ic x 9 taps x 128 oc
    const int x0  = blockIdx.x * 64;
    const int y   = blockIdx.y;
    const int oc0 = blockIdx.z * 128;
    const int tid = threadIdx.x;
    const int tx  = tid & 15;        // px group
    const int ty  = tid >> 4;        // oc group
    const int px0 = tx * 4;
    const int ocl = ty * 8;

    float acc[8][4];
#pragma unroll
    for (int o = 0; o < 8; ++o)
#pragma unroll
        for (int p = 0; p < 4; ++p) acc[o][p] = 0.f;

    for (int icb = 0; icb < 32; ++icb) {
        const int ic0 = icb * 8;
        // input patch: rows y-1..y+1, cols x0-1..x0+64 (66 valid of 68)
        for (int l = tid; l < 8 * 3 * 68; l += 256) {
            int c = l % 68;
            int rest = l / 68;
            int r = rest % 3, ic = rest / 3;
            int gx = x0 - 1 + c;
            int gy = y - 1 + r;
            float v = 0.f;
            if (c < 66 && gx >= 0 && gx < WW && gy >= 0 && gy < HH)
                v = f[(ic0 + ic) * NPIX + gy * WW + gx];
            sx[ic][r][c] = v;
        }
        // weights: g_wt[(ic0+ic)*9+k][oc0+oc]  (coalesced, conflict-free STS)
        for (int l = tid; l < 8 * 9 * 128; l += 256) {
            int oc = l & 127;
            int rk = l >> 7;            // 0..71
            int ic = rk / 9, k = rk % 9;
            sw[ic][k][oc] = g_wt[((ic0 + ic) * 9 + k) * 256 + oc0 + oc];
        }
        __syncthreads();
#pragma unroll 4
        for (int ic = 0; ic < 8; ++ic) {
#pragma unroll
            for (int ky = 0; ky < 3; ++ky) {
                float4 xa = *(const float4*)&sx[ic][ky][px0];
                float2 xb = *(const float2*)&sx[ic][ky][px0 + 4];
                float xv[6] = {xa.x, xa.y, xa.z, xa.w, xb.x, xb.y};
#pragma unroll
                for (int kx = 0; kx < 3; ++kx) {
                    const float* wp = &sw[ic][ky * 3 + kx][ocl];
                    float4 w0 = *(const float4*)wp;
                    float4 w1v = *(const float4*)(wp + 4);
                    float wr[8] = {w0.x, w0.y, w0.z, w0.w,
                                   w1v.x, w1v.y, w1v.z, w1v.w};
#pragma unroll
                    for (int o = 0; o < 8; ++o)
#pragma unroll
                        for (int p = 0; p < 4; ++p)
                            acc[o][p] += wr[o] * xv[kx + p];
                }
            }
        }
        __syncthreads();
    }
#pragma unroll
    for (int o = 0; o < 8; ++o) {
        int oc = oc0 + ocl + o;
        float b = b1[oc];
#pragma unroll
        for (int p = 0; p < 4; ++p) {
            int gx = x0 + px0 + p;
            if (gx < WW)
                g_x[oc * NPIX + y * WW + gx] = fmaxf(acc[o][p] + b, 0.f);
        }
    }
}

// ---------------- 3: 1x1 heads (cls 9 + reg 36) + keys + histogram ----------
__global__ void __launch_bounds__(128) heads_k(const float* __restrict__ wcls,
                                               const float* __restrict__ bcls,
                                               const float* __restrict__ wreg,
                                               const float* __restrict__ breg) {
    __shared__ float swc[9 * 256];
    __shared__ float swr[36 * 256];
    const int t = threadIdx.x;
    for (int l = t; l < 9 * 256; l += 128)  swc[l] = wcls[l];
    for (int l = t; l < 36 * 256; l += 128) swr[l] = wreg[l];
    __syncthreads();
    const int p = blockIdx.x * 128 + t;

    float c[9], r[36];
#pragma unroll
    for (int a = 0; a < 9; ++a)  c[a] = bcls[a];
#pragma unroll
    for (int o = 0; o < 36; ++o) r[o] = breg[o];

    for (int ic = 0; ic < 256; ic += 2) {
        float xv0 = g_x[ic * NPIX + p];
        float xv1 = g_x[(ic + 1) * NPIX + p];
#pragma unroll
        for (int a = 0; a < 9; ++a)
            c[a] += xv0 * swc[a * 256 + ic] + xv1 * swc[a * 256 + ic + 1];
#pragma unroll
        for (int o = 0; o < 36; ++o)
            r[o] += xv0 * swr[o * 256 + ic] + xv1 * swr[o * 256 + ic + 1];
    }
#pragma unroll
    for (int a = 0; a < 9; ++a) {
        int n = p * 9 + a;
        unsigned k = fkey(c[a]);
        g_key[n] = k;
        atomicAdd(&g_hist[k >> 16], 1);
        g_off4[n] = make_float4(r[4 * a], r[4 * a + 1], r[4 * a + 2], r[4 * a + 3]);
    }
}

// ---------------- 4: find boundary top-16 bin -------------------------------
__global__ void scan1_k() {
    __shared__ int cs[256];
    int t = threadIdx.x;
    int s = 0;
    for (int k = 0; k < 256; ++k) s += g_hist[t * 256 + k];
    cs[t] = s;
    __syncthreads();
    if (t == 0) {
        long long S = 0;
        int tc = 0;
        for (int cch = 255; cch >= 0; --cch) {
            if (S + cs[cch] >= PRE_NMS) { tc = cch; break; }
            S += cs[cch];
        }
        for (int b = tc * 256 + 255;; --b) {
            if (S + g_hist[b] >= PRE_NMS || b == tc * 256) {
                g_B = b;
                g_need = PRE_NMS - (int)S;
                break;
            }
            S += g_hist[b];
        }
    }
}

// ---------------- 5: low-16 histogram within boundary bin -------------------
__global__ void hist2_k() {
    int i = blockIdx.x * 256 + threadIdx.x;
    if (i < NANCH) {
        unsigned k = g_key[i];
        if ((int)(k >> 16) == g_B) atomicAdd(&g_hist2[k & 0xFFFFu], 1);
    }
}

// ---------------- 6: exact 32-bit threshold ---------------------------------
__global__ void scan2_k() {
    __shared__ int cs[256];
    int t = threadIdx.x;
    int s = 0;
    for (int k = 0; k < 256; ++k) s += g_hist2[t * 256 + k];
    cs[t] = s;
    __syncthreads();
    if (t == 0) {
        int need = g_need;
        long long S = 0;
        int tc = 0;
        for (int cch = 255; cch >= 0; --cch) {
            if (S + cs[cch] >= need) { tc = cch; break; }
            S += cs[cch];
        }
        int L = tc * 256;
        for (int b = tc * 256 + 255;; --b) {
            if (S + g_hist2[b] >= need || b == tc * 256) { L = b; break; }
            S += g_hist2[b];
        }
        g_T = ((unsigned)g_B << 16) | (unsigned)L;
    }
}

// ---------------- 7: compact survivors --------------------------------------
__global__ void compact_k() {
    int i = blockIdx.x * 256 + threadIdx.x;
    if (i < NANCH) {
        unsigned k = g_key[i];
        if (k >= g_T) {
            int pos = atomicAdd(&g_cnt, 1);
            if (pos < CAND_CAP)
                g_cand[pos] = ((unsigned long long)k << 32) |
                              (unsigned long long)(0xFFFFFFFFu - (unsigned)i);
        }
    }
}

// ---------------- 8: bitonic sort (desc key, asc index ties) ----------------
__global__ void __launch_bounds__(1024) sort_k() {
    extern __shared__ unsigned long long s[];
    int t = threadIdx.x;
    int cnt = g_cnt;
    if (cnt > CAND_CAP) cnt = CAND_CAP;
    for (int l = t; l < CAND_CAP; l += 1024)
        s[l] = (l < cnt) ? g_cand[l] : 0ULL;
    __syncthreads();
    for (int k = 2; k <= CAND_CAP; k <<= 1) {
        for (int j = k >> 1; j > 0; j >>= 1) {
            for (int idx = t; idx < CAND_CAP; idx += 1024) {
                int ixj = idx ^ j;
                if (ixj > idx) {
                    unsigned long long va = s[idx], vb = s[ixj];
                    bool up = ((idx & k) == 0);           // descending
                    if (up ? (va < vb) : (va > vb)) { s[idx] = vb; s[ixj] = va; }
                }
            }
            __syncthreads();
        }
    }
    for (int l = t; l < PRE_NMS; l += 1024)
        g_sel[l] = (int)(0xFFFFFFFFu - (unsigned)s[l]);
}

// ---------------- 9: decode + clip + min-size -------------------------------
__global__ void decode_k(const int* __restrict__ imh, const int* __restrict__ imw) {
    int i = blockIdx.x * 256 + threadIdx.x;
    if (i >= NBOX_PAD) return;
    if (i >= PRE_NMS) { g_props[i] = make_float4(0.f, 0.f, 0.f, 0.f); return; }
    int n = g_sel[i];
    int a = n % 9, p = n / 9;
    int x = p % WW, y = p / WW;
    float cx0 = (x + 0.5f) * 4.f, cy0 = (y + 0.5f) * 4.f;
    float x1a = cx0 - 0.5f * c_aw[a], x2a = cx0 + 0.5f * c_aw[a];
    float y1a = cy0 - 0.5f * c_ah[a], y2a = cy0 + 0.5f * c_ah[a];
    float wa = x2a - x1a, ha = y2a - y1a;
    float cxa = x1a + 0.5f * wa, cya = y1a + 0.5f * ha;
    float4 d = g_off4[n];
    float cx = d.x * wa + cxa, cy = d.y * ha + cya;
    float w = expf(d.z) * wa, h = expf(d.w) * ha;
    float W = (float)imw[0], H = (float)imh[0];
    float x1 = fminf(fmaxf(cx - 0.5f * w, 0.f), W);
    float y1 = fminf(fmaxf(cy - 0.5f * h, 0.f), H);
    float x2 = fminf(fmaxf(cx + 0.5f * w, 0.f), W);
    float y2 = fminf(fmaxf(cy + 0.5f * h, 0.f), H);
    g_props[i] = make_float4(x1, y1, x2, y2);
    g_valid[i] = ((x2 - x1) >= 1.f) && ((y2 - y1) >= 1.f);
}

// ---------------- 10: IoU bitmask (6000 x 188 words) ------------------------
__global__ void __launch_bounds__(256) iou_k() {
    __shared__ float4 jb[32];
    const int wcol = blockIdx.x;
    const int i = blockIdx.y * 256 + threadIdx.x;
    if (threadIdx.x < 32) jb[threadIdx.x] = g_props[wcol * 32 + threadIdx.x];
    __syncthreads();
    if (i >= PRE_NMS) return;
    float4 a = g_props[i];
    float areaA = (a.z - a.x) * (a.w - a.y);
    unsigned m = 0;
#pragma unroll 4
    for (int k = 0; k < 32; ++k) {
        float4 b = jb[k];
        float areaB = (b.z - b.x) * (b.w - b.y);
        float lx = fmaxf(a.x, b.x), ly = fmaxf(a.y, b.y);
        float rx = fminf(a.z, b.z), ry = fminf(a.w, b.w);
        float iw = fmaxf(rx - lx, 0.f), ih = fmaxf(ry - ly, 0.f);
        float inter = iw * ih;
        float iou = __fdiv_rn(inter, areaA + areaB - inter + 1e-9f);
        if (iou > 0.7f) m |= (1u << k);
    }
    g_mask[i * NWORDS + wcol] = m;
}

// ---------------- 11: serial greedy NMS reduce (cp.async row prefetch) ------
#define PF 12
__device__ __forceinline__ void cpa4(void* smem, const void* g) {
    unsigned s = (unsigned)__cvta_generic_to_shared(smem);
    asm volatile("cp.async.ca.shared.global [%0], [%1], 4;" ::"r"(s), "l"(g));
}
__global__ void __launch_bounds__(256) nmsred_k() {
    __shared__ unsigned remv[NWORDS];
    __shared__ unsigned ring[16][NWORDS];
    __shared__ int sflag;
    const int t = threadIdx.x;
    if (t < NWORDS) remv[t] = 0;
    for (int rr = 0; rr < PF; ++rr) {
        if (t < NWORDS) cpa4(&ring[rr][t], &g_mask[rr * NWORDS + t]);
        asm volatile("cp.async.commit_group;");
    }
    __syncthreads();
    for (int i = 0; i < PRE_NMS; ++i) {
        if (i + PF < PRE_NMS && t < NWORDS)
            cpa4(&ring[(i + PF) & 15][t], &g_mask[(i + PF) * NWORDS + t]);
        asm volatile("cp.async.commit_group;");
        asm volatile("cp.async.wait_group %0;" ::"n"(PF));
        __syncthreads();
        if (t == 0) {
            int kp = g_valid[i] && !((remv[i >> 5] >> (i & 31)) & 1u);
            sflag = kp;
            g_keep[i] = kp;
        }
        __syncthreads();
        if (sflag && t < NWORDS) remv[t] |= ring[i & 15][t];
    }
}

// ---------------- 12: compact kept boxes into output ------------------------
__global__ void __launch_bounds__(256) out_k(float* __restrict__ out) {
    __shared__ int pre[257];
    const int t = threadIdx.x;
    const int base = t * 24;
    int s = 0;
    for (int k = 0; k < 24; ++k) {
        int i = base + k;
        if (i < PRE_NMS && g_keep[i]) s++;
    }
    pre[t + 1] = s;
    if (t == 0) pre[0] = 0;
    __syncthreads();
    if (t == 0)
        for (int k = 1; k <= 256; ++k) pre[k] += pre[k - 1];
    __syncthreads();
    int rank = pre[t];
    for (int k = 0; k < 24; ++k) {
        int i = base + k;
        if (i < PRE_NMS && g_keep[i]) {
            if (rank < POST_NMS) {
                float4 b = g_props[i];
                out[rank * 4 + 0] = b.x;
                out[rank * 4 + 1] = b.y;
                out[rank * 4 + 2] = b.z;
                out[rank * 4 + 3] = b.w;
            }
            rank++;
        }
    }
}

// ---------------- launcher ---------------------------------------------------
extern "C" void kernel_launch(void* const* d_in, const int* in_sizes, int n_in,
                              void* d_out, int out_size) {
    const float* feature = (const float*)d_in[0];
    const float* w1   = (const float*)d_in[1];
    const float* b1   = (const float*)d_in[2];
    const float* wcls = (const float*)d_in[3];
    const float* bcls = (const float*)d_in[4];
    const float* wreg = (const float*)d_in[5];
    const float* breg = (const float*)d_in[6];
    const int*   imh  = (const int*)d_in[7];
    const int*   imw  = (const int*)d_in[8];
    float* out = (float*)d_out;

    cudaFuncSetAttribute(sort_k, cudaFuncAttributeMaxDynamicSharedMemorySize,
                         CAND_CAP * 8);

    zero_k<<<256, 256>>>(out);
    transw_k<<<(256 * 2304 + 255) / 256, 256>>>(w1);
    conv3x3_k<<<dim3(5, 200, 2), 256>>>(feature, b1);
    heads_k<<<NPIX / 128, 128>>>(wcls, bcls, wreg, breg);
    scan1_k<<<1, 256>>>();
    hist2_k<<<(NANCH + 255) / 256, 256>>>();
    scan2_k<<<1, 256>>>();
    compact_k<<<(NANCH + 255) / 256, 256>>>();
    sort_k<<<1, 1024, CAND_CAP * 8>>>();
    decode_k<<<(NBOX_PAD + 255) / 256, 256>>>(imh, imw);
    iou_k<<<dim3(NWORDS, (PRE_NMS + 255) / 256), 256>>>();
    nmsred_k<<<1, 256>>>();
    out_k<<<1, 256>>>(out);
}

// round 4
// speedup vs baseline: 1.4161x; 1.4161x over previous
#include <cuda_runtime.h>
#include <cstdint>

#define HH 200
#define WW 272
#define NPIX 54400
#define NANCH 489600
#define PRE_NMS 6000
#define NWORDS 188
#define NBOX_PAD 6016
#define POST_NMS 1000
#define CAND_CAP 8192

// ---------------- scratch ----------------------------------------------------
__device__ float        g_x[256 * NPIX];
__device__ float        g_wt[2304 * 256];
__device__ unsigned     g_key[NANCH];
__device__ float4       g_off4[NANCH];
__device__ int          g_hist[65536];
__device__ int          g_hist2[65536];
__device__ int          g_B, g_need;
__device__ unsigned     g_T;
__device__ int          g_cnt;
__device__ unsigned long long g_cand[CAND_CAP];
__device__ int          g_sel[PRE_NMS];
__device__ float4       g_props[NBOX_PAD];
__device__ unsigned     g_invalid[NWORDS];
__device__ unsigned     g_mask[PRE_NMS * NWORDS];
__device__ int          g_keep[PRE_NMS];

__device__ __constant__ float c_aw[9] = {
    45.254833995939045f, 32.f, 22.627416997969522f,
    90.50966799187809f,  64.f, 45.254833995939045f,
    181.01933598375618f, 128.f, 90.50966799187809f};
__device__ __constant__ float c_ah[9] = {
    22.627416997969522f, 32.f, 45.254833995939045f,
    45.254833995939045f, 64.f, 90.50966799187809f,
    90.50966799187809f,  128.f, 181.01933598375618f};

__device__ __forceinline__ unsigned fkey(float f) {
    unsigned u = __float_as_uint(f);
    return (u & 0x80000000u) ? ~u : (u | 0x80000000u);
}

// ---------------- 0: zero scratch + output ----------------------------------
__global__ void zero_k(float* out) {
    int i = blockIdx.x * 256 + threadIdx.x;
    if (i < 65536) { g_hist[i] = 0; g_hist2[i] = 0; }
    if (i == 0) g_cnt = 0;
    if (i < NWORDS) g_invalid[i] = 0;
    if (i < POST_NMS * 4) out[i] = 0.f;
}

// ---------------- 1: transpose conv1 weights --------------------------------
__global__ void transw_k(const float* __restrict__ w1) {
    int i = blockIdx.x * 256 + threadIdx.x;
    if (i < 256 * 2304) {
        int oc = i / 2304, r = i % 2304;
        g_wt[r * 256 + oc] = w1[i];
    }
}

// ---------------- 2: 3x3 conv 256->256 + bias + relu ------------------------
// grid (5, 100, 2), block 256. Tile: 128 oc x 64 px x 2 rows.
// Per-output FMA order is (ic, ky, kx) sequential — bit-identical to the
// round-1 passing kernel (matches reference accumulation realization).
__global__ void __launch_bounds__(256) conv3x3_k(const float* __restrict__ f,
                                                 const float* __restrict__ b1) {
    __shared__ __align__(16) float sx[8][4][68];     // 8 ic x 4 rows x 66(+pad)
    __shared__ __align__(16) float sw[8][9][128];    // 8 ic x 9 taps x 128 oc
    const int x0  = blockIdx.x * 64;
    const int y0  = blockIdx.y * 2;
    const int oc0 = blockIdx.z * 128;
    const int tid = threadIdx.x;
    const int tx  = tid & 15;        // px group
    const int ty  = tid >> 4;        // oc group
    const int px0 = tx * 4;
    const int ocl = ty * 8;

    float acc[8][2][4];
#pragma unroll
    for (int o = 0; o < 8; ++o)
#pragma unroll
        for (int yy = 0; yy < 2; ++yy)
#pragma unroll
            for (int p = 0; p < 4; ++p) acc[o][yy][p] = 0.f;

    for (int icb = 0; icb < 32; ++icb) {
        const int ic0 = icb * 8;
        // input patch: rows y0-1..y0+2, cols x0-1..x0+64
        for (int l = tid; l < 8 * 4 * 68; l += 256) {
            int c = l % 68;
            int rest = l / 68;
            int r = rest & 3, ic = rest >> 2;
            int gx = x0 - 1 + c;
            int gy = y0 - 1 + r;
            float v = 0.f;
            if (c < 66 && gx >= 0 && gx < WW && gy >= 0 && gy < HH)
                v = f[(ic0 + ic) * NPIX + gy * WW + gx];
            sx[ic][r][c] = v;
        }
        for (int l = tid; l < 8 * 9 * 128; l += 256) {
            int oc = l & 127;
            int rk = l >> 7;
            int ic = rk / 9, k = rk % 9;
            sw[ic][k][oc] = g_wt[((ic0 + ic) * 9 + k) * 256 + oc0 + oc];
        }
        __syncthreads();
#pragma unroll 4
        for (int ic = 0; ic < 8; ++ic) {
#pragma unroll
            for (int ky = 0; ky < 3; ++ky) {
                float4 xa0 = *(const float4*)&sx[ic][ky][px0];
                float2 xb0 = *(const float2*)&sx[ic][ky][px0 + 4];
                float4 xa1 = *(const float4*)&sx[ic][ky + 1][px0];
                float2 xb1 = *(const float2*)&sx[ic][ky + 1][px0 + 4];
                float xv0[6] = {xa0.x, xa0.y, xa0.z, xa0.w, xb0.x, xb0.y};
                float xv1[6] = {xa1.x, xa1.y, xa1.z, xa1.w, xb1.x, xb1.y};
#pragma unroll
                for (int kx = 0; kx < 3; ++kx) {
                    const float* wp = &sw[ic][ky * 3 + kx][ocl];
                    float4 w0 = *(const float4*)wp;
                    float4 w1v = *(const float4*)(wp + 4);
                    float wr[8] = {w0.x, w0.y, w0.z, w0.w,
                                   w1v.x, w1v.y, w1v.z, w1v.w};
#pragma unroll
                    for (int o = 0; o < 8; ++o) {
#pragma unroll
                        for (int p = 0; p < 4; ++p)
                            acc[o][0][p] += wr[o] * xv0[kx + p];
#pragma unroll
                        for (int p = 0; p < 4; ++p)
                            acc[o][1][p] += wr[o] * xv1[kx + p];
                    }
                }
            }
        }
        __syncthreads();
    }
#pragma unroll
    for (int o = 0; o < 8; ++o) {
        int oc = oc0 + ocl + o;
        float b = b1[oc];
#pragma unroll
        for (int yy = 0; yy < 2; ++yy) {
            int y = y0 + yy;
#pragma unroll
            for (int p = 0; p < 4; ++p) {
                int gx = x0 + px0 + p;
                if (gx < WW)
                    g_x[oc * NPIX + y * WW + gx] =
                        fmaxf(acc[o][yy][p] + b, 0.f);
            }
        }
    }
}

// ---------------- 3: 1x1 heads (2 px/thread, float4 weight LDS) -------------
// Per-output accumulation keeps round-1's pairwise form:
//   c += x_even*w_even + x_odd*w_odd   (two ic per statement, ic ascending)
__global__ void __launch_bounds__(128) heads_k(const float* __restrict__ wcls,
                                               const float* __restrict__ bcls,
                                               const float* __restrict__ wreg,
                                               const float* __restrict__ breg) {
    __shared__ float4 swc[9 * 64];
    __shared__ float4 swr[36 * 64];
    const int t = threadIdx.x;
    for (int l = t; l < 9 * 64; l += 128)  swc[l] = ((const float4*)wcls)[l];
    for (int l = t; l < 36 * 64; l += 128) swr[l] = ((const float4*)wreg)[l];
    __syncthreads();
    const int p0 = blockIdx.x * 256 + t;
    const int p1 = p0 + 128;
    const bool v1 = (p1 < NPIX);

    float c0[9], c1[9], r0[36], r1[36];
#pragma unroll
    for (int a = 0; a < 9; ++a) { c0[a] = bcls[a]; c1[a] = bcls[a]; }
#pragma unroll
    for (int o = 0; o < 36; ++o) { r0[o] = breg[o]; r1[o] = breg[o]; }

    for (int icq = 0; icq < 64; ++icq) {
        const int ic = icq * 4;
        float xa0 = g_x[ic * NPIX + p0];
        float xa1 = g_x[(ic + 1) * NPIX + p0];
        float xa2 = g_x[(ic + 2) * NPIX + p0];
        float xa3 = g_x[(ic + 3) * NPIX + p0];
        float xb0 = 0.f, xb1 = 0.f, xb2 = 0.f, xb3 = 0.f;
        if (v1) {
            xb0 = g_x[ic * NPIX + p1];
            xb1 = g_x[(ic + 1) * NPIX + p1];
            xb2 = g_x[(ic + 2) * NPIX + p1];
            xb3 = g_x[(ic + 3) * NPIX + p1];
        }
#pragma unroll
        for (int a = 0; a < 9; ++a) {
            float4 w = swc[a * 64 + icq];
            c0[a] += xa0 * w.x + xa1 * w.y;
            c0[a] += xa2 * w.z + xa3 * w.w;
            c1[a] += xb0 * w.x + xb1 * w.y;
            c1[a] += xb2 * w.z + xb3 * w.w;
        }
#pragma unroll
        for (int o = 0; o < 36; ++o) {
            float4 w = swr[o * 64 + icq];
            r0[o] += xa0 * w.x + xa1 * w.y;
            r0[o] += xa2 * w.z + xa3 * w.w;
            r1[o] += xb0 * w.x + xb1 * w.y;
            r1[o] += xb2 * w.z + xb3 * w.w;
        }
    }
#pragma unroll
    for (int a = 0; a < 9; ++a) {
        int n = p0 * 9 + a;
        unsigned k = fkey(c0[a]);
        g_key[n] = k;
        atomicAdd(&g_hist[k >> 16], 1);
        g_off4[n] = make_float4(r0[4 * a], r0[4 * a + 1], r0[4 * a + 2],
                                r0[4 * a + 3]);
    }
    if (v1) {
#pragma unroll
        for (int a = 0; a < 9; ++a) {
            int n = p1 * 9 + a;
            unsigned k = fkey(c1[a]);
            g_key[n] = k;
            atomicAdd(&g_hist[k >> 16], 1);
            g_off4[n] = make_float4(r1[4 * a], r1[4 * a + 1], r1[4 * a + 2],
                                    r1[4 * a + 3]);
        }
    }
}

// ---------------- 4: find boundary top-16 bin -------------------------------
__global__ void scan1_k() {
    __shared__ int cs[256];
    int t = threadIdx.x;
    int s = 0;
    for (int k = 0; k < 256; ++k) s += g_hist[t * 256 + k];
    cs[t] = s;
    __syncthreads();
    if (t == 0) {
        long long S = 0;
        int tc = 0;
        for (int cch = 255; cch >= 0; --cch) {
            if (S + cs[cch] >= PRE_NMS) { tc = cch; break; }
            S += cs[cch];
        }
        for (int b = tc * 256 + 255;; --b) {
            if (S + g_hist[b] >= PRE_NMS || b == tc * 256) {
                g_B = b;
                g_need = PRE_NMS - (int)S;
                break;
            }
            S += g_hist[b];
        }
    }
}

// ---------------- 5: low-16 histogram within boundary bin -------------------
__global__ void hist2_k() {
    int i = blockIdx.x * 256 + threadIdx.x;
    if (i < NANCH) {
        unsigned k = g_key[i];
        if ((int)(k >> 16) == g_B) atomicAdd(&g_hist2[k & 0xFFFFu], 1);
    }
}

// ---------------- 6: exact 32-bit threshold ---------------------------------
__global__ void scan2_k() {
    __shared__ int cs[256];
    int t = threadIdx.x;
    int s = 0;
    for (int k = 0; k < 256; ++k) s += g_hist2[t * 256 + k];
    cs[t] = s;
    __syncthreads();
    if (t == 0) {
        int need = g_need;
        long long S = 0;
        int tc = 0;
        for (int cch = 255; cch >= 0; --cch) {
            if (S + cs[cch] >= need) { tc = cch; break; }
            S += cs[cch];
        }
        int L = tc * 256;
        for (int b = tc * 256 + 255;; --b) {
            if (S + g_hist2[b] >= need || b == tc * 256) { L = b; break; }
            S += g_hist2[b];
        }
        g_T = ((unsigned)g_B << 16) | (unsigned)L;
    }
}

// ---------------- 7: compact survivors --------------------------------------
__global__ void compact_k() {
    int i = blockIdx.x * 256 + threadIdx.x;
    if (i < NANCH) {
        unsigned k = g_key[i];
        if (k >= g_T) {
            int pos = atomicAdd(&g_cnt, 1);
            if (pos < CAND_CAP)
                g_cand[pos] = ((unsigned long long)k << 32) |
                              (unsigned long long)(0xFFFFFFFFu - (unsigned)i);
        }
    }
}

// ---------------- 8: bitonic sort (desc key, asc index ties) ----------------
__global__ void __launch_bounds__(1024) sort_k() {
    extern __shared__ unsigned long long s[];
    int t = threadIdx.x;
    int cnt = g_cnt;
    if (cnt > CAND_CAP) cnt = CAND_CAP;
    for (int l = t; l < CAND_CAP; l += 1024)
        s[l] = (l < cnt) ? g_cand[l] : 0ULL;
    __syncthreads();
    for (int k = 2; k <= CAND_CAP; k <<= 1) {
        for (int j = k >> 1; j > 0; j >>= 1) {
            for (int idx = t; idx < CAND_CAP; idx += 1024) {
                int ixj = idx ^ j;
                if (ixj > idx) {
                    unsigned long long va = s[idx], vb = s[ixj];
                    bool up = ((idx & k) == 0);
                    if (up ? (va < vb) : (va > vb)) { s[idx] = vb; s[ixj] = va; }
                }
            }
            __syncthreads();
        }
    }
    for (int l = t; l < PRE_NMS; l += 1024)
        g_sel[l] = (int)(0xFFFFFFFFu - (unsigned)s[l]);
}

// ---------------- 9: decode + clip + min-size -------------------------------
__global__ void decode_k(const int* __restrict__ imh, const int* __restrict__ imw) {
    int i = blockIdx.x * 256 + threadIdx.x;
    if (i >= NBOX_PAD) return;
    if (i >= PRE_NMS) { g_props[i] = make_float4(0.f, 0.f, 0.f, 0.f); return; }
    int n = g_sel[i];
    int a = n % 9, p = n / 9;
    int x = p % WW, y = p / WW;
    float cx0 = (x + 0.5f) * 4.f, cy0 = (y + 0.5f) * 4.f;
    float x1a = cx0 - 0.5f * c_aw[a], x2a = cx0 + 0.5f * c_aw[a];
    float y1a = cy0 - 0.5f * c_ah[a], y2a = cy0 + 0.5f * c_ah[a];
    float wa = x2a - x1a, ha = y2a - y1a;
    float cxa = x1a + 0.5f * wa, cya = y1a + 0.5f * ha;
    float4 d = g_off4[n];
    float cx = d.x * wa + cxa, cy = d.y * ha + cya;
    float w = expf(d.z) * wa, h = expf(d.w) * ha;
    float W = (float)imw[0], H = (float)imh[0];
    float x1 = fminf(fmaxf(cx - 0.5f * w, 0.f), W);
    float y1 = fminf(fmaxf(cy - 0.5f * h, 0.f), H);
    float x2 = fminf(fmaxf(cx + 0.5f * w, 0.f), W);
    float y2 = fminf(fmaxf(cy + 0.5f * h, 0.f), H);
    g_props[i] = make_float4(x1, y1, x2, y2);
    bool valid = ((x2 - x1) >= 1.f) && ((y2 - y1) >= 1.f);
    if (!valid) atomicOr(&g_invalid[i >> 5], 1u << (i & 31));
}

// ---------------- 10: IoU bitmask (6000 x 188 words) ------------------------
__global__ void __launch_bounds__(256) iou_k() {
    __shared__ float4 jb[32];
    const int wcol = blockIdx.x;
    const int i = blockIdx.y * 256 + threadIdx.x;
    if (threadIdx.x < 32) jb[threadIdx.x] = g_props[wcol * 32 + threadIdx.x];
    __syncthreads();
    if (i >= PRE_NMS) return;
    float4 a = g_props[i];
    float areaA = (a.z - a.x) * (a.w - a.y);
    unsigned m = 0;
#pragma unroll 4
    for (int k = 0; k < 32; ++k) {
        float4 b = jb[k];
        float areaB = (b.z - b.x) * (b.w - b.y);
        float lx = fmaxf(a.x, b.x), ly = fmaxf(a.y, b.y);
        float rx = fminf(a.z, b.z), ry = fminf(a.w, b.w);
        float iw = fmaxf(rx - lx, 0.f), ih = fmaxf(ry - ly, 0.f);
        float inter = iw * ih;
        float iou = __fdiv_rn(inter, areaA + areaB - inter + 1e-9f);
        if (iou > 0.7f) m |= (1u << k);
    }
    g_mask[i * NWORDS + wcol] = m;
}

// ---------------- 11: single-warp register-resident NMS reduce ---------------
__global__ void __launch_bounds__(32) nmsred_k() {
    const int t = threadIdx.x;
    unsigned remv[6];
#pragma unroll
    for (int j = 0; j < 6; ++j) {
        int w = j * 32 + t;
        remv[j] = (w < NWORDS) ? g_invalid[w] : 0u;
    }
    unsigned row[8][6];
#pragma unroll
    for (int r = 0; r < 8; ++r)
#pragma unroll
        for (int j = 0; j < 6; ++j) {
            int w = j * 32 + t;
            row[r][j] = (w < NWORDS) ? g_mask[r * NWORDS + w] : 0u;
        }
#pragma unroll
    for (int slot = 0; slot < 6; ++slot) {
        const int iend = (slot + 1) * 1024 < PRE_NMS ? (slot + 1) * 1024 : PRE_NMS;
        for (int ib = slot * 1024; ib < iend; ib += 8) {
#pragma unroll
            for (int r = 0; r < 8; ++r) {
                const int i = ib + r;
                const int wi = i >> 5;
                const int owner = wi & 31;
                unsigned b = (remv[slot] >> (i & 31)) & 1u;
                unsigned sup = __shfl_sync(0xFFFFFFFFu, b, owner);
                int kp = !sup;
                if (t == 0) g_keep[i] = kp;
                if (kp) {
#pragma unroll
                    for (int j = 0; j < 6; ++j) remv[j] |= row[r][j];
                }
                const int ni = i + 8;
                if (ni < PRE_NMS) {
#pragma unroll
                    for (int j = 0; j < 6; ++j) {
                        int w = j * 32 + t;
                        row[r][j] = (w < NWORDS) ? g_mask[ni * NWORDS + w] : 0u;
                    }
                }
            }
        }
    }
}

// ---------------- 12: compact kept boxes into output ------------------------
__global__ void __launch_bounds__(256) out_k(float* __restrict__ out) {
    __shared__ int pre[257];
    const int t = threadIdx.x;
    const int base = t * 24;
    int s = 0;
    for (int k = 0; k < 24; ++k) {
        int i = base + k;
        if (i < PRE_NMS && g_keep[i]) s++;
    }
    pre[t + 1] = s;
    if (t == 0) pre[0] = 0;
    __syncthreads();
    if (t == 0)
        for (int k = 1; k <= 256; ++k) pre[k] += pre[k - 1];
    __syncthreads();
    int rank = pre[t];
    for (int k = 0; k < 24; ++k) {
        int i = base + k;
        if (i < PRE_NMS && g_keep[i]) {
            if (rank < POST_NMS) {
                float4 b = g_props[i];
                out[rank * 4 + 0] = b.x;
                out[rank * 4 + 1] = b.y;
                out[rank * 4 + 2] = b.z;
                out[rank * 4 + 3] = b.w;
            }
            rank++;
        }
    }
}

// ---------------- launcher ---------------------------------------------------
extern "C" void kernel_launch(void* const* d_in, const int* in_sizes, int n_in,
                              void* d_out, int out_size) {
    const float* feature = (const float*)d_in[0];
    const float* w1   = (const float*)d_in[1];
    const float* b1   = (const float*)d_in[2];
    const float* wcls = (const float*)d_in[3];
    const float* bcls = (const float*)d_in[4];
    const float* wreg = (const float*)d_in[5];
    const float* breg = (const float*)d_in[6];
    const int*   imh  = (const int*)d_in[7];
    const int*   imw  = (const int*)d_in[8];
    float* out = (float*)d_out;

    cudaFuncSetAttribute(sort_k, cudaFuncAttributeMaxDynamicSharedMemorySize,
                         CAND_CAP * 8);

    zero_k<<<256, 256>>>(out);
    transw_k<<<(256 * 2304 + 255) / 256, 256>>>(w1);
    conv3x3_k<<<dim3(5, 100, 2), 256>>>(feature, b1);
    heads_k<<<(NPIX + 255) / 256, 128>>>(wcls, bcls, wreg, breg);
    scan1_k<<<1, 256>>>();
    hist2_k<<<(NANCH + 255) / 256, 256>>>();
    scan2_k<<<1, 256>>>();
    compact_k<<<(NANCH + 255) / 256, 256>>>();
    sort_k<<<1, 1024, CAND_CAP * 8>>>();
    decode_k<<<(NBOX_PAD + 255) / 256, 256>>>(imh, imw);
    iou_k<<<dim3(NWORDS, (PRE_NMS + 255) / 256), 256>>>();
    nmsred_k<<<1, 32>>>();
    out_k<<<1, 256>>>(out);
}

// round 5
// speedup vs baseline: 1.5207x; 1.0739x over previous
#include <cuda_runtime.h>
#include <cstdint>

#define HH 200
#define WW 272
#define NPIX 54400
#define NANCH 489600
#define PRE_NMS 6000
#define NWORDS 188
#define NBOX_PAD 6016
#define POST_NMS 1000
#define CAND_CAP 8192

typedef unsigned long long ull;

// ---------------- scratch ----------------------------------------------------
__device__ float        g_x[256 * NPIX];
__device__ float        g_wt[2304 * 256];
__device__ unsigned     g_key[NANCH];
__device__ float4       g_off4[NANCH];
__device__ int          g_hist[65536];
__device__ int          g_hist2[65536];
__device__ int          g_B, g_need;
__device__ unsigned     g_T;
__device__ int          g_cnt;
__device__ unsigned long long g_cand[CAND_CAP];
__device__ int          g_sel[PRE_NMS];
__device__ float4       g_props[NBOX_PAD];
__device__ unsigned     g_invalid[NWORDS];
__device__ unsigned     g_mask[PRE_NMS * NWORDS];
__device__ int          g_keep[PRE_NMS];

__device__ __constant__ float c_aw[9] = {
    45.254833995939045f, 32.f, 22.627416997969522f,
    90.50966799187809f,  64.f, 45.254833995939045f,
    181.01933598375618f, 128.f, 90.50966799187809f};
__device__ __constant__ float c_ah[9] = {
    22.627416997969522f, 32.f, 45.254833995939045f,
    45.254833995939045f, 64.f, 90.50966799187809f,
    90.50966799187809f,  128.f, 181.01933598375618f};

__device__ __forceinline__ unsigned fkey(float f) {
    unsigned u = __float_as_uint(f);
    return (u & 0x80000000u) ? ~u : (u | 0x80000000u);
}

// ---------------- f32x2 packed helpers (SASS FFMA2) --------------------------
__device__ __forceinline__ void fma2(ull& acc, ull x, ull w) {
    asm("fma.rn.f32x2 %0, %1, %2, %0;" : "+l"(acc) : "l"(x), "l"(w));
}
__device__ __forceinline__ ull pack2(float lo, float hi) {
    ull d;
    asm("mov.b64 %0, {%1, %2};" : "=l"(d) : "f"(lo), "f"(hi));
    return d;
}
__device__ __forceinline__ void unpack2(float& lo, float& hi, ull v) {
    asm("mov.b64 {%0, %1}, %2;" : "=f"(lo), "=f"(hi) : "l"(v));
}

// ---------------- 0: zero scratch + output ----------------------------------
__global__ void zero_k(float* out) {
    int i = blockIdx.x * 256 + threadIdx.x;
    if (i < 65536) { g_hist[i] = 0; g_hist2[i] = 0; }
    if (i == 0) g_cnt = 0;
    if (i < NWORDS) g_invalid[i] = 0;
    if (i < POST_NMS * 4) out[i] = 0.f;
}

// ---------------- 1: transpose conv1 weights --------------------------------
__global__ void transw_k(const float* __restrict__ w1) {
    int i = blockIdx.x * 256 + threadIdx.x;
    if (i < 256 * 2304) {
        int oc = i / 2304, r = i % 2304;
        g_wt[r * 256 + oc] = w1[i];
    }
}

// ---------------- 2: 3x3 conv 256->256 + bias + relu (FFMA2) ----------------
// grid (5, 100, 2), block 256. Tile: 128 oc x 64 px x 2 rows.
// Each f32x2 lane carries one output channel's accumulator; the per-lane FMA
// sequence is (ic, ky, kx) sequential — bit-identical to the passing round-1/4
// kernels (fma.rn.f32x2 rounds each lane exactly like scalar FFMA).
__global__ void __launch_bounds__(256, 2) conv3x3_k(const float* __restrict__ f,
                                                    const float* __restrict__ b1) {
    __shared__ __align__(16) float sx[8][4][68];     // 8 ic x 4 rows x 66(+pad)
    __shared__ __align__(16) float sw[8][9][128];    // 8 ic x 9 taps x 128 oc
    const int x0  = blockIdx.x * 64;
    const int y0  = blockIdx.y * 2;
    const int oc0 = blockIdx.z * 128;
    const int tid = threadIdx.x;
    const int tx  = tid & 15;        // px group
    const int ty  = tid >> 4;        // oc group
    const int px0 = tx * 4;
    const int ocl = ty * 8;

    // acc2[opair][row][px]: lanes = (oc 2*opair, oc 2*opair+1)
    ull acc2[4][2][4];
#pragma unroll
    for (int op = 0; op < 4; ++op)
#pragma unroll
        for (int yy = 0; yy < 2; ++yy)
#pragma unroll
            for (int p = 0; p < 4; ++p) acc2[op][yy][p] = 0ULL;

    for (int icb = 0; icb < 32; ++icb) {
        const int ic0 = icb * 8;
        for (int l = tid; l < 8 * 4 * 68; l += 256) {
            int c = l % 68;
            int rest = l / 68;
            int r = rest & 3, ic = rest >> 2;
            int gx = x0 - 1 + c;
            int gy = y0 - 1 + r;
            float v = 0.f;
            if (c < 66 && gx >= 0 && gx < WW && gy >= 0 && gy < HH)
                v = f[(ic0 + ic) * NPIX + gy * WW + gx];
            sx[ic][r][c] = v;
        }
        for (int l = tid; l < 8 * 9 * 128; l += 256) {
            int oc = l & 127;
            int rk = l >> 7;
            int ic = rk / 9, k = rk % 9;
            sw[ic][k][oc] = g_wt[((ic0 + ic) * 9 + k) * 256 + oc0 + oc];
        }
        __syncthreads();
#pragma unroll 2
        for (int ic = 0; ic < 8; ++ic) {
#pragma unroll
            for (int ky = 0; ky < 3; ++ky) {
                float4 xa0 = *(const float4*)&sx[ic][ky][px0];
                float2 xb0 = *(const float2*)&sx[ic][ky][px0 + 4];
                float4 xa1 = *(const float4*)&sx[ic][ky + 1][px0];
                float2 xb1 = *(const float2*)&sx[ic][ky + 1][px0 + 4];
                const float xv0[6] = {xa0.x, xa0.y, xa0.z, xa0.w, xb0.x, xb0.y};
                const float xv1[6] = {xa1.x, xa1.y, xa1.z, xa1.w, xb1.x, xb1.y};
                ull xp0[6], xp1[6];
#pragma unroll
                for (int j = 0; j < 6; ++j) {
                    xp0[j] = pack2(xv0[j], xv0[j]);
                    xp1[j] = pack2(xv1[j], xv1[j]);
                }
#pragma unroll
                for (int kx = 0; kx < 3; ++kx) {
                    const ull* wp = (const ull*)&sw[ic][ky * 3 + kx][ocl];
                    ull w0 = wp[0], w1 = wp[1], w2 = wp[2], w3 = wp[3];
#pragma unroll
                    for (int p = 0; p < 4; ++p) {
                        fma2(acc2[0][0][p], xp0[kx + p], w0);
                        fma2(acc2[1][0][p], xp0[kx + p], w1);
                        fma2(acc2[2][0][p], xp0[kx + p], w2);
                        fma2(acc2[3][0][p], xp0[kx + p], w3);
                        fma2(acc2[0][1][p], xp1[kx + p], w0);
                        fma2(acc2[1][1][p], xp1[kx + p], w1);
                        fma2(acc2[2][1][p], xp1[kx + p], w2);
                        fma2(acc2[3][1][p], xp1[kx + p], w3);
                    }
                }
            }
        }
        __syncthreads();
    }
#pragma unroll
    for (int op = 0; op < 4; ++op) {
        int oce = oc0 + ocl + 2 * op;
        float be = b1[oce];
        float bo = b1[oce + 1];
#pragma unroll
        for (int yy = 0; yy < 2; ++yy) {
            int y = y0 + yy;
#pragma unroll
            for (int p = 0; p < 4; ++p) {
                float ae, ao;
                unpack2(ae, ao, acc2[op][yy][p]);
                int gx = x0 + px0 + p;
                if (gx < WW) {
                    g_x[oce * NPIX + y * WW + gx] = fmaxf(ae + be, 0.f);
                    g_x[(oce + 1) * NPIX + y * WW + gx] = fmaxf(ao + bo, 0.f);
                }
            }
        }
    }
}

// ---------------- 3: 1x1 heads (2 px/thread, float4 weight LDS) -------------
__global__ void __launch_bounds__(128) heads_k(const float* __restrict__ wcls,
                                               const float* __restrict__ bcls,
                                               const float* __restrict__ wreg,
                                               const float* __restrict__ breg) {
    __shared__ float4 swc[9 * 64];
    __shared__ float4 swr[36 * 64];
    const int t = threadIdx.x;
    for (int l = t; l < 9 * 64; l += 128)  swc[l] = ((const float4*)wcls)[l];
    for (int l = t; l < 36 * 64; l += 128) swr[l] = ((const float4*)wreg)[l];
    __syncthreads();
    const int p0 = blockIdx.x * 256 + t;
    const int p1 = p0 + 128;
    const bool v1 = (p1 < NPIX);

    float c0[9], c1[9], r0[36], r1[36];
#pragma unroll
    for (int a = 0; a < 9; ++a) { c0[a] = bcls[a]; c1[a] = bcls[a]; }
#pragma unroll
    for (int o = 0; o < 36; ++o) { r0[o] = breg[o]; r1[o] = breg[o]; }

    for (int icq = 0; icq < 64; ++icq) {
        const int ic = icq * 4;
        float xa0 = g_x[ic * NPIX + p0];
        float xa1 = g_x[(ic + 1) * NPIX + p0];
        float xa2 = g_x[(ic + 2) * NPIX + p0];
        float xa3 = g_x[(ic + 3) * NPIX + p0];
        float xb0 = 0.f, xb1 = 0.f, xb2 = 0.f, xb3 = 0.f;
        if (v1) {
            xb0 = g_x[ic * NPIX + p1];
            xb1 = g_x[(ic + 1) * NPIX + p1];
            xb2 = g_x[(ic + 2) * NPIX + p1];
            xb3 = g_x[(ic + 3) * NPIX + p1];
        }
#pragma unroll
        for (int a = 0; a < 9; ++a) {
            float4 w = swc[a * 64 + icq];
            c0[a] += xa0 * w.x + xa1 * w.y;
            c0[a] += xa2 * w.z + xa3 * w.w;
            c1[a] += xb0 * w.x + xb1 * w.y;
            c1[a] += xb2 * w.z + xb3 * w.w;
        }
#pragma unroll
        for (int o = 0; o < 36; ++o) {
            float4 w = swr[o * 64 + icq];
            r0[o] += xa0 * w.x + xa1 * w.y;
            r0[o] += xa2 * w.z + xa3 * w.w;
            r1[o] += xb0 * w.x + xb1 * w.y;
            r1[o] += xb2 * w.z + xb3 * w.w;
        }
    }
#pragma unroll
    for (int a = 0; a < 9; ++a) {
        int n = p0 * 9 + a;
        unsigned k = fkey(c0[a]);
        g_key[n] = k;
        atomicAdd(&g_hist[k >> 16], 1);
        g_off4[n] = make_float4(r0[4 * a], r0[4 * a + 1], r0[4 * a + 2],
                                r0[4 * a + 3]);
    }
    if (v1) {
#pragma unroll
        for (int a = 0; a < 9; ++a) {
            int n = p1 * 9 + a;
            unsigned k = fkey(c1[a]);
            g_key[n] = k;
            atomicAdd(&g_hist[k >> 16], 1);
            g_off4[n] = make_float4(r1[4 * a], r1[4 * a + 1], r1[4 * a + 2],
                                    r1[4 * a + 3]);
        }
    }
}

// ---------------- 4: find boundary top-16 bin -------------------------------
__global__ void scan1_k() {
    __shared__ int cs[256];
    int t = threadIdx.x;
    int s = 0;
    for (int k = 0; k < 256; ++k) s += g_hist[t * 256 + k];
    cs[t] = s;
    __syncthreads();
    if (t == 0) {
        long long S = 0;
        int tc = 0;
        for (int cch = 255; cch >= 0; --cch) {
            if (S + cs[cch] >= PRE_NMS) { tc = cch; break; }
            S += cs[cch];
        }
        for (int b = tc * 256 + 255;; --b) {
            if (S + g_hist[b] >= PRE_NMS || b == tc * 256) {
                g_B = b;
                g_need = PRE_NMS - (int)S;
                break;
            }
            S += g_hist[b];
        }
    }
}

// ---------------- 5: low-16 histogram within boundary bin -------------------
__global__ void hist2_k() {
    int i = blockIdx.x * 256 + threadIdx.x;
    if (i < NANCH) {
        unsigned k = g_key[i];
        if ((int)(k >> 16) == g_B) atomicAdd(&g_hist2[k & 0xFFFFu], 1);
    }
}

// ---------------- 6: exact 32-bit threshold ---------------------------------
__global__ void scan2_k() {
    __shared__ int cs[256];
    int t = threadIdx.x;
    int s = 0;
    for (int k = 0; k < 256; ++k) s += g_hist2[t * 256 + k];
    cs[t] = s;
    __syncthreads();
    if (t == 0) {
        int need = g_need;
        long long S = 0;
        int tc = 0;
        for (int cch = 255; cch >= 0; --cch) {
            if (S + cs[cch] >= need) { tc = cch; break; }
            S += cs[cch];
        }
        int L = tc * 256;
        for (int b = tc * 256 + 255;; --b) {
            if (S + g_hist2[b] >= need || b == tc * 256) { L = b; break; }
            S += g_hist2[b];
        }
        g_T = ((unsigned)g_B << 16) | (unsigned)L;
    }
}

// ---------------- 7: compact survivors --------------------------------------
__global__ void compact_k() {
    int i = blockIdx.x * 256 + threadIdx.x;
    if (i < NANCH) {
        unsigned k = g_key[i];
        if (k >= g_T) {
            int pos = atomicAdd(&g_cnt, 1);
            if (pos < CAND_CAP)
                g_cand[pos] = ((unsigned long long)k << 32) |
                              (unsigned long long)(0xFFFFFFFFu - (unsigned)i);
        }
    }
}

// ---------------- 8: bitonic sort (desc key, asc index ties) ----------------
__global__ void __launch_bounds__(1024) sort_k() {
    extern __shared__ unsigned long long s[];
    int t = threadIdx.x;
    int cnt = g_cnt;
    if (cnt > CAND_CAP) cnt = CAND_CAP;
    for (int l = t; l < CAND_CAP; l += 1024)
        s[l] = (l < cnt) ? g_cand[l] : 0ULL;
    __syncthreads();
    for (int k = 2; k <= CAND_CAP; k <<= 1) {
        for (int j = k >> 1; j > 0; j >>= 1) {
            for (int idx = t; idx < CAND_CAP; idx += 1024) {
                int ixj = idx ^ j;
                if (ixj > idx) {
                    unsigned long long va = s[idx], vb = s[ixj];
                    bool up = ((idx & k) == 0);
                    if (up ? (va < vb) : (va > vb)) { s[idx] = vb; s[ixj] = va; }
                }
            }
            __syncthreads();
        }
    }
    for (int l = t; l < PRE_NMS; l += 1024)
        g_sel[l] = (int)(0xFFFFFFFFu - (unsigned)s[l]);
}

// ---------------- 9: decode + clip + min-size -------------------------------
__global__ void decode_k(const int* __restrict__ imh, const int* __restrict__ imw) {
    int i = blockIdx.x * 256 + threadIdx.x;
    if (i >= NBOX_PAD) return;
    if (i >= PRE_NMS) { g_props[i] = make_float4(0.f, 0.f, 0.f, 0.f); return; }
    int n = g_sel[i];
    int a = n % 9, p = n / 9;
    int x = p % WW, y = p / WW;
    float cx0 = (x + 0.5f) * 4.f, cy0 = (y + 0.5f) * 4.f;
    float x1a = cx0 - 0.5f * c_aw[a], x2a = cx0 + 0.5f * c_aw[a];
    float y1a = cy0 - 0.5f * c_ah[a], y2a = cy0 + 0.5f * c_ah[a];
    float wa = x2a - x1a, ha = y2a - y1a;
    float cxa = x1a + 0.5f * wa, cya = y1a + 0.5f * ha;
    float4 d = g_off4[n];
    float cx = d.x * wa + cxa, cy = d.y * ha + cya;
    float w = expf(d.z) * wa, h = expf(d.w) * ha;
    float W = (float)imw[0], H = (float)imh[0];
    float x1 = fminf(fmaxf(cx - 0.5f * w, 0.f), W);
    float y1 = fminf(fmaxf(cy - 0.5f * h, 0.f), H);
    float x2 = fminf(fmaxf(cx + 0.5f * w, 0.f), W);
    float y2 = fminf(fmaxf(cy + 0.5f * h, 0.f), H);
    g_props[i] = make_float4(x1, y1, x2, y2);
    bool valid = ((x2 - x1) >= 1.f) && ((y2 - y1) >= 1.f);
    if (!valid) atomicOr(&g_invalid[i >> 5], 1u << (i & 31));
}

// ---------------- 10: IoU bitmask (6000 x 188 words) ------------------------
__global__ void __launch_bounds__(256) iou_k() {
    __shared__ float4 jb[32];
    const int wcol = blockIdx.x;
    const int i = blockIdx.y * 256 + threadIdx.x;
    if (threadIdx.x < 32) jb[threadIdx.x] = g_props[wcol * 32 + threadIdx.x];
    __syncthreads();
    if (i >= PRE_NMS) return;
    float4 a = g_props[i];
    float areaA = (a.z - a.x) * (a.w - a.y);
    unsigned m = 0;
#pragma unroll 4
    for (int k = 0; k < 32; ++k) {
        float4 b = jb[k];
        float areaB = (b.z - b.x) * (b.w - b.y);
        float lx = fmaxf(a.x, b.x), ly = fmaxf(a.y, b.y);
        float rx = fminf(a.z, b.z), ry = fminf(a.w, b.w);
        float iw = fmaxf(rx - lx, 0.f), ih = fmaxf(ry - ly, 0.f);
        float inter = iw * ih;
        float iou = __fdiv_rn(inter, areaA + areaB - inter + 1e-9f);
        if (iou > 0.7f) m |= (1u << k);
    }
    g_mask[i * NWORDS + wcol] = m;
}

// ---------------- 11: single-warp register-resident NMS reduce ---------------
__global__ void __launch_bounds__(32) nmsred_k() {
    const int t = threadIdx.x;
    unsigned remv[6];
#pragma unroll
    for (int j = 0; j < 6; ++j) {
        int w = j * 32 + t;
        remv[j] = (w < NWORDS) ? g_invalid[w] : 0u;
    }
    unsigned row[8][6];
#pragma unroll
    for (int r = 0; r < 8; ++r)
#pragma unroll
        for (int j = 0; j < 6; ++j) {
            int w = j * 32 + t;
            row[r][j] = (w < NWORDS) ? g_mask[r * NWORDS + w] : 0u;
        }
#pragma unroll
    for (int slot = 0; slot < 6; ++slot) {
        const int iend = (slot + 1) * 1024 < PRE_NMS ? (slot + 1) * 1024 : PRE_NMS;
        for (int ib = slot * 1024; ib < iend; ib += 8) {
#pragma unroll
            for (int r = 0; r < 8; ++r) {
                const int i = ib + r;
                const int wi = i >> 5;
                const int owner = wi & 31;
                unsigned b = (remv[slot] >> (i & 31)) & 1u;
                unsigned sup = __shfl_sync(0xFFFFFFFFu, b, owner);
                int kp = !sup;
                if (t == 0) g_keep[i] = kp;
                if (kp) {
#pragma unroll
                    for (int j = 0; j < 6; ++j) remv[j] |= row[r][j];
                }
                const int ni = i + 8;
                if (ni < PRE_NMS) {
#pragma unroll
                    for (int j = 0; j < 6; ++j) {
                        int w = j * 32 + t;
                        row[r][j] = (w < NWORDS) ? g_mask[ni * NWORDS + w] : 0u;
                    }
                }
            }
        }
    }
}

// ---------------- 12: compact kept boxes into output ------------------------
__global__ void __launch_bounds__(256) out_k(float* __restrict__ out) {
    __shared__ int pre[257];
    const int t = threadIdx.x;
    const int base = t * 24;
    int s = 0;
    for (int k = 0; k < 24; ++k) {
        int i = base + k;
        if (i < PRE_NMS && g_keep[i]) s++;
    }
    pre[t + 1] = s;
    if (t == 0) pre[0] = 0;
    __syncthreads();
    if (t == 0)
        for (int k = 1; k <= 256; ++k) pre[k] += pre[k - 1];
    __syncthreads();
    int rank = pre[t];
    for (int k = 0; k < 24; ++k) {
        int i = base + k;
        if (i < PRE_NMS && g_keep[i]) {
            if (rank < POST_NMS) {
                float4 b = g_props[i];
                out[rank * 4 + 0] = b.x;
                out[rank * 4 + 1] = b.y;
                out[rank * 4 + 2] = b.z;
                out[rank * 4 + 3] = b.w;
            }
            rank++;
        }
    }
}

// ---------------- launcher ---------------------------------------------------
extern "C" void kernel_launch(void* const* d_in, const int* in_sizes, int n_in,
                              void* d_out, int out_size) {
    const float* feature = (const float*)d_in[0];
    const float* w1   = (const float*)d_in[1];
    const float* b1   = (const float*)d_in[2];
    const float* wcls = (const float*)d_in[3];
    const float* bcls = (const float*)d_in[4];
    const float* wreg = (const float*)d_in[5];
    const float* breg = (const float*)d_in[6];
    const int*   imh  = (const int*)d_in[7];
    const int*   imw  = (const int*)d_in[8];
    float* out = (float*)d_out;

    cudaFuncSetAttribute(sort_k, cudaFuncAttributeMaxDynamicSharedMemorySize,
                         CAND_CAP * 8);

    zero_k<<<256, 256>>>(out);
    transw_k<<<(256 * 2304 + 255) / 256, 256>>>(w1);
    conv3x3_k<<<dim3(5, 100, 2), 256>>>(feature, b1);
    heads_k<<<(NPIX + 255) / 256, 128>>>(wcls, bcls, wreg, breg);
    scan1_k<<<1, 256>>>();
    hist2_k<<<(NANCH + 255) / 256, 256>>>();
    scan2_k<<<1, 256>>>();
    compact_k<<<(NANCH + 255) / 256, 256>>>();
    sort_k<<<1, 1024, CAND_CAP * 8>>>();
    decode_k<<<(NBOX_PAD + 255) / 256, 256>>>(imh, imw);
    iou_k<<<dim3(NWORDS, (PRE_NMS + 255) / 256), 256>>>();
    nmsred_k<<<1, 32>>>();
    out_k<<<1, 256>>>(out);
}

// round 6
// speedup vs baseline: 1.5428x; 1.0145x over previous
#include <cuda_runtime.h>
#include <cstdint>

#define HH 200
#define WW 272
#define NPIX 54400
#define NANCH 489600
#define PRE_NMS 6000
#define NWORDS 188
#define NBOX_PAD 6016
#define POST_NMS 1000
#define CAND_CAP 8192

typedef unsigned long long ull;

// ---------------- scratch ----------------------------------------------------
__device__ float        g_x[256 * NPIX];
__device__ float        g_wt[2304 * 256];
__device__ unsigned     g_key[NANCH];
__device__ float4       g_off4[NANCH];
__device__ int          g_hist[65536];
__device__ int          g_hist2[65536];
__device__ int          g_B, g_need;
__device__ unsigned     g_T;
__device__ int          g_cnt;
__device__ unsigned long long g_cand[CAND_CAP];
__device__ int          g_sel[PRE_NMS];
__device__ float4       g_props[NBOX_PAD];
__device__ unsigned     g_invalid[NWORDS];
__device__ unsigned     g_mask[PRE_NMS * NWORDS];
__device__ int          g_keep[PRE_NMS];

__device__ __constant__ float c_aw[9] = {
    45.254833995939045f, 32.f, 22.627416997969522f,
    90.50966799187809f,  64.f, 45.254833995939045f,
    181.01933598375618f, 128.f, 90.50966799187809f};
__device__ __constant__ float c_ah[9] = {
    22.627416997969522f, 32.f, 45.254833995939045f,
    45.254833995939045f, 64.f, 90.50966799187809f,
    90.50966799187809f,  128.f, 181.01933598375618f};

__device__ __forceinline__ unsigned fkey(float f) {
    unsigned u = __float_as_uint(f);
    return (u & 0x80000000u) ? ~u : (u | 0x80000000u);
}

// ---------------- f32x2 packed helpers (SASS FFMA2) --------------------------
__device__ __forceinline__ void fma2(ull& acc, ull x, ull w) {
    asm("fma.rn.f32x2 %0, %1, %2, %0;" : "+l"(acc) : "l"(x), "l"(w));
}
__device__ __forceinline__ ull pack2(float lo, float hi) {
    ull d;
    asm("mov.b64 %0, {%1, %2};" : "=l"(d) : "f"(lo), "f"(hi));
    return d;
}
__device__ __forceinline__ void unpack2(float& lo, float& hi, ull v) {
    asm("mov.b64 {%0, %1}, %2;" : "=f"(lo), "=f"(hi) : "l"(v));
}

// ---------------- 0: zero scratch + output ----------------------------------
__global__ void zero_k(float* out) {
    int i = blockIdx.x * 256 + threadIdx.x;
    if (i < 65536) { g_hist[i] = 0; g_hist2[i] = 0; }
    if (i == 0) g_cnt = 0;
    if (i < NWORDS) g_invalid[i] = 0;
    if (i < POST_NMS * 4) out[i] = 0.f;
}

// ---------------- 1: transpose conv1 weights --------------------------------
__global__ void transw_k(const float* __restrict__ w1) {
    int i = blockIdx.x * 256 + threadIdx.x;
    if (i < 256 * 2304) {
        int oc = i / 2304, r = i % 2304;
        g_wt[r * 256 + oc] = w1[i];
    }
}

// ---------------- 2: 3x3 conv 256->256 + bias + relu (FFMA2) ----------------
// grid (5, 100, 2), block 256. Tile: 128 oc x 64 px x 2 rows.
// No min-blocks clamp: let registers float so the packed accumulators and
// broadcast temporaries stay in registers (no spills). Per-lane FMA sequence
// remains (ic, ky, kx) sequential — bit-identical to rounds 1/4/5.
__global__ void __launch_bounds__(256) conv3x3_k(const float* __restrict__ f,
                                                 const float* __restrict__ b1) {
    __shared__ __align__(16) float sx[8][4][68];     // 8 ic x 4 rows x 66(+pad)
    __shared__ __align__(16) float sw[8][9][128];    // 8 ic x 9 taps x 128 oc
    const int x0  = blockIdx.x * 64;
    const int y0  = blockIdx.y * 2;
    const int oc0 = blockIdx.z * 128;
    const int tid = threadIdx.x;
    const int tx  = tid & 15;        // px group
    const int ty  = tid >> 4;        // oc group
    const int px0 = tx * 4;
    const int ocl = ty * 8;

    // acc2[opair][row][px]: lanes = (oc 2*opair, oc 2*opair+1)
    ull acc2[4][2][4];
#pragma unroll
    for (int op = 0; op < 4; ++op)
#pragma unroll
        for (int yy = 0; yy < 2; ++yy)
#pragma unroll
            for (int p = 0; p < 4; ++p) acc2[op][yy][p] = 0ULL;

    for (int icb = 0; icb < 32; ++icb) {
        const int ic0 = icb * 8;
        for (int l = tid; l < 8 * 4 * 68; l += 256) {
            int c = l % 68;
            int rest = l / 68;
            int r = rest & 3, ic = rest >> 2;
            int gx = x0 - 1 + c;
            int gy = y0 - 1 + r;
            float v = 0.f;
            if (c < 66 && gx >= 0 && gx < WW && gy >= 0 && gy < HH)
                v = f[(ic0 + ic) * NPIX + gy * WW + gx];
            sx[ic][r][c] = v;
        }
        for (int l = tid; l < 8 * 9 * 128; l += 256) {
            int oc = l & 127;
            int rk = l >> 7;
            int ic = rk / 9, k = rk % 9;
            sw[ic][k][oc] = g_wt[((ic0 + ic) * 9 + k) * 256 + oc0 + oc];
        }
        __syncthreads();
#pragma unroll 2
        for (int ic = 0; ic < 8; ++ic) {
#pragma unroll
            for (int ky = 0; ky < 3; ++ky) {
                float4 xa0 = *(const float4*)&sx[ic][ky][px0];
                float2 xb0 = *(const float2*)&sx[ic][ky][px0 + 4];
                float4 xa1 = *(const float4*)&sx[ic][ky + 1][px0];
                float2 xb1 = *(const float2*)&sx[ic][ky + 1][px0 + 4];
                const float xv0[6] = {xa0.x, xa0.y, xa0.z, xa0.w, xb0.x, xb0.y};
                const float xv1[6] = {xa1.x, xa1.y, xa1.z, xa1.w, xb1.x, xb1.y};
                ull xp0[6], xp1[6];
#pragma unroll
                for (int j = 0; j < 6; ++j) {
                    xp0[j] = pack2(xv0[j], xv0[j]);
                    xp1[j] = pack2(xv1[j], xv1[j]);
                }
#pragma unroll
                for (int kx = 0; kx < 3; ++kx) {
                    const ull* wp = (const ull*)&sw[ic][ky * 3 + kx][ocl];
                    ull w0 = wp[0], w1 = wp[1], w2 = wp[2], w3 = wp[3];
#pragma unroll
                    for (int p = 0; p < 4; ++p) {
                        fma2(acc2[0][0][p], xp0[kx + p], w0);
                        fma2(acc2[1][0][p], xp0[kx + p], w1);
                        fma2(acc2[2][0][p], xp0[kx + p], w2);
                        fma2(acc2[3][0][p], xp0[kx + p], w3);
                        fma2(acc2[0][1][p], xp1[kx + p], w0);
                        fma2(acc2[1][1][p], xp1[kx + p], w1);
                        fma2(acc2[2][1][p], xp1[kx + p], w2);
                        fma2(acc2[3][1][p], xp1[kx + p], w3);
                    }
                }
            }
        }
        __syncthreads();
    }
#pragma unroll
    for (int op = 0; op < 4; ++op) {
        int oce = oc0 + ocl + 2 * op;
        float be = b1[oce];
        float bo = b1[oce + 1];
#pragma unroll
        for (int yy = 0; yy < 2; ++yy) {
            int y = y0 + yy;
#pragma unroll
            for (int p = 0; p < 4; ++p) {
                float ae, ao;
                unpack2(ae, ao, acc2[op][yy][p]);
                int gx = x0 + px0 + p;
                if (gx < WW) {
                    g_x[oce * NPIX + y * WW + gx] = fmaxf(ae + be, 0.f);
                    g_x[(oce + 1) * NPIX + y * WW + gx] = fmaxf(ao + bo, 0.f);
                }
            }
        }
    }
}

// ---------------- 3: 1x1 heads (2 px/thread, float4 weight LDS) -------------
__global__ void __launch_bounds__(128) heads_k(const float* __restrict__ wcls,
                                               const float* __restrict__ bcls,
                                               const float* __restrict__ wreg,
                                               const float* __restrict__ breg) {
    __shared__ float4 swc[9 * 64];
    __shared__ float4 swr[36 * 64];
    const int t = threadIdx.x;
    for (int l = t; l < 9 * 64; l += 128)  swc[l] = ((const float4*)wcls)[l];
    for (int l = t; l < 36 * 64; l += 128) swr[l] = ((const float4*)wreg)[l];
    __syncthreads();
    const int p0 = blockIdx.x * 256 + t;
    const int p1 = p0 + 128;
    const bool v1 = (p1 < NPIX);

    float c0[9], c1[9], r0[36], r1[36];
#pragma unroll
    for (int a = 0; a < 9; ++a) { c0[a] = bcls[a]; c1[a] = bcls[a]; }
#pragma unroll
    for (int o = 0; o < 36; ++o) { r0[o] = breg[o]; r1[o] = breg[o]; }

    for (int icq = 0; icq < 64; ++icq) {
        const int ic = icq * 4;
        float xa0 = g_x[ic * NPIX + p0];
        float xa1 = g_x[(ic + 1) * NPIX + p0];
        float xa2 = g_x[(ic + 2) * NPIX + p0];
        float xa3 = g_x[(ic + 3) * NPIX + p0];
        float xb0 = 0.f, xb1 = 0.f, xb2 = 0.f, xb3 = 0.f;
        if (v1) {
            xb0 = g_x[ic * NPIX + p1];
            xb1 = g_x[(ic + 1) * NPIX + p1];
            xb2 = g_x[(ic + 2) * NPIX + p1];
            xb3 = g_x[(ic + 3) * NPIX + p1];
        }
#pragma unroll
        for (int a = 0; a < 9; ++a) {
            float4 w = swc[a * 64 + icq];
            c0[a] += xa0 * w.x + xa1 * w.y;
            c0[a] += xa2 * w.z + xa3 * w.w;
            c1[a] += xb0 * w.x + xb1 * w.y;
            c1[a] += xb2 * w.z + xb3 * w.w;
        }
#pragma unroll
        for (int o = 0; o < 36; ++o) {
            float4 w = swr[o * 64 + icq];
            r0[o] += xa0 * w.x + xa1 * w.y;
            r0[o] += xa2 * w.z + xa3 * w.w;
            r1[o] += xb0 * w.x + xb1 * w.y;
            r1[o] += xb2 * w.z + xb3 * w.w;
        }
    }
#pragma unroll
    for (int a = 0; a < 9; ++a) {
        int n = p0 * 9 + a;
        unsigned k = fkey(c0[a]);
        g_key[n] = k;
        atomicAdd(&g_hist[k >> 16], 1);
        g_off4[n] = make_float4(r0[4 * a], r0[4 * a + 1], r0[4 * a + 2],
                                r0[4 * a + 3]);
    }
    if (v1) {
#pragma unroll
        for (int a = 0; a < 9; ++a) {
            int n = p1 * 9 + a;
            unsigned k = fkey(c1[a]);
            g_key[n] = k;
            atomicAdd(&g_hist[k >> 16], 1);
            g_off4[n] = make_float4(r1[4 * a], r1[4 * a + 1], r1[4 * a + 2],
                                    r1[4 * a + 3]);
        }
    }
}

// ---------------- 4: find boundary top-16 bin -------------------------------
__global__ void scan1_k() {
    __shared__ int cs[256];
    int t = threadIdx.x;
    int s = 0;
    for (int k = 0; k < 256; ++k) s += g_hist[t * 256 + k];
    cs[t] = s;
    __syncthreads();
    if (t == 0) {
        long long S = 0;
        int tc = 0;
        for (int cch = 255; cch >= 0; --cch) {
            if (S + cs[cch] >= PRE_NMS) { tc = cch; break; }
            S += cs[cch];
        }
        for (int b = tc * 256 + 255;; --b) {
            if (S + g_hist[b] >= PRE_NMS || b == tc * 256) {
                g_B = b;
                g_need = PRE_NMS - (int)S;
                break;
            }
            S += g_hist[b];
        }
    }
}

// ---------------- 5: low-16 histogram within boundary bin -------------------
__global__ void hist2_k() {
    int i = blockIdx.x * 256 + threadIdx.x;
    if (i < NANCH) {
        unsigned k = g_key[i];
        if ((int)(k >> 16) == g_B) atomicAdd(&g_hist2[k & 0xFFFFu], 1);
    }
}

// ---------------- 6: exact 32-bit threshold ---------------------------------
__global__ void scan2_k() {
    __shared__ int cs[256];
    int t = threadIdx.x;
    int s = 0;
    for (int k = 0; k < 256; ++k) s += g_hist2[t * 256 + k];
    cs[t] = s;
    __syncthreads();
    if (t == 0) {
        int need = g_need;
        long long S = 0;
        int tc = 0;
        for (int cch = 255; cch >= 0; --cch) {
            if (S + cs[cch] >= need) { tc = cch; break; }
            S += cs[cch];
        }
        int L = tc * 256;
        for (int b = tc * 256 + 255;; --b) {
            if (S + g_hist2[b] >= need || b == tc * 256) { L = b; break; }
            S += g_hist2[b];
        }
        g_T = ((unsigned)g_B << 16) | (unsigned)L;
    }
}

// ---------------- 7: compact survivors --------------------------------------
__global__ void compact_k() {
    int i = blockIdx.x * 256 + threadIdx.x;
    if (i < NANCH) {
        unsigned k = g_key[i];
        if (k >= g_T) {
            int pos = atomicAdd(&g_cnt, 1);
            if (pos < CAND_CAP)
                g_cand[pos] = ((unsigned long long)k << 32) |
                              (unsigned long long)(0xFFFFFFFFu - (unsigned)i);
        }
    }
}

// ---------------- 8: bitonic sort (desc key, asc index ties) ----------------
__global__ void __launch_bounds__(1024) sort_k() {
    extern __shared__ unsigned long long s[];
    int t = threadIdx.x;
    int cnt = g_cnt;
    if (cnt > CAND_CAP) cnt = CAND_CAP;
    for (int l = t; l < CAND_CAP; l += 1024)
        s[l] = (l < cnt) ? g_cand[l] : 0ULL;
    __syncthreads();
    for (int k = 2; k <= CAND_CAP; k <<= 1) {
        for (int j = k >> 1; j > 0; j >>= 1) {
            for (int idx = t; idx < CAND_CAP; idx += 1024) {
                int ixj = idx ^ j;
                if (ixj > idx) {
                    unsigned long long va = s[idx], vb = s[ixj];
                    bool up = ((idx & k) == 0);
                    if (up ? (va < vb) : (va > vb)) { s[idx] = vb; s[ixj] = va; }
                }
            }
            __syncthreads();
        }
    }
    for (int l = t; l < PRE_NMS; l += 1024)
        g_sel[l] = (int)(0xFFFFFFFFu - (unsigned)s[l]);
}

// ---------------- 9: decode + clip + min-size -------------------------------
__global__ void decode_k(const int* __restrict__ imh, const int* __restrict__ imw) {
    int i = blockIdx.x * 256 + threadIdx.x;
    if (i >= NBOX_PAD) return;
    if (i >= PRE_NMS) { g_props[i] = make_float4(0.f, 0.f, 0.f, 0.f); return; }
    int n = g_sel[i];
    int a = n % 9, p = n / 9;
    int x = p % WW, y = p / WW;
    float cx0 = (x + 0.5f) * 4.f, cy0 = (y + 0.5f) * 4.f;
    float x1a = cx0 - 0.5f * c_aw[a], x2a = cx0 + 0.5f * c_aw[a];
    float y1a = cy0 - 0.5f * c_ah[a], y2a = cy0 + 0.5f * c_ah[a];
    float wa = x2a - x1a, ha = y2a - y1a;
    float cxa = x1a + 0.5f * wa, cya = y1a + 0.5f * ha;
    float4 d = g_off4[n];
    float cx = d.x * wa + cxa, cy = d.y * ha + cya;
    float w = expf(d.z) * wa, h = expf(d.w) * ha;
    float W = (float)imw[0], H = (float)imh[0];
    float x1 = fminf(fmaxf(cx - 0.5f * w, 0.f), W);
    float y1 = fminf(fmaxf(cy - 0.5f * h, 0.f), H);
    float x2 = fminf(fmaxf(cx + 0.5f * w, 0.f), W);
    float y2 = fminf(fmaxf(cy + 0.5f * h, 0.f), H);
    g_props[i] = make_float4(x1, y1, x2, y2);
    bool valid = ((x2 - x1) >= 1.f) && ((y2 - y1) >= 1.f);
    if (!valid) atomicOr(&g_invalid[i >> 5], 1u << (i & 31));
}

// ---------------- 10: IoU bitmask (6000 x 188 words) ------------------------
__global__ void __launch_bounds__(256) iou_k() {
    __shared__ float4 jb[32];
    const int wcol = blockIdx.x;
    const int i = blockIdx.y * 256 + threadIdx.x;
    if (threadIdx.x < 32) jb[threadIdx.x] = g_props[wcol * 32 + threadIdx.x];
    __syncthreads();
    if (i >= PRE_NMS) return;
    float4 a = g_props[i];
    float areaA = (a.z - a.x) * (a.w - a.y);
    unsigned m = 0;
#pragma unroll 4
    for (int k = 0; k < 32; ++k) {
        float4 b = jb[k];
        float areaB = (b.z - b.x) * (b.w - b.y);
        float lx = fmaxf(a.x, b.x), ly = fmaxf(a.y, b.y);
        float rx = fminf(a.z, b.z), ry = fminf(a.w, b.w);
        float iw = fmaxf(rx - lx, 0.f), ih = fmaxf(ry - ly, 0.f);
        float inter = iw * ih;
        float iou = __fdiv_rn(inter, areaA + areaB - inter + 1e-9f);
        if (iou > 0.7f) m |= (1u << k);
    }
    g_mask[i * NWORDS + wcol] = m;
}

// ---------------- 11: single-warp register-resident NMS reduce ---------------
__global__ void __launch_bounds__(32) nmsred_k() {
    const int t = threadIdx.x;
    unsigned remv[6];
#pragma unroll
    for (int j = 0; j < 6; ++j) {
        int w = j * 32 + t;
        remv[j] = (w < NWORDS) ? g_invalid[w] : 0u;
    }
    unsigned row[8][6];
#pragma unroll
    for (int r = 0; r < 8; ++r)
#pragma unroll
        for (int j = 0; j < 6; ++j) {
            int w = j * 32 + t;
            row[r][j] = (w < NWORDS) ? g_mask[r * NWORDS + w] : 0u;
        }
#pragma unroll
    for (int slot = 0; slot < 6; ++slot) {
        const int iend = (slot + 1) * 1024 < PRE_NMS ? (slot + 1) * 1024 : PRE_NMS;
        for (int ib = slot * 1024; ib < iend; ib += 8) {
#pragma unroll
            for (int r = 0; r < 8; ++r) {
                const int i = ib + r;
                const int wi = i >> 5;
                const int owner = wi & 31;
                unsigned b = (remv[slot] >> (i & 31)) & 1u;
                unsigned sup = __shfl_sync(0xFFFFFFFFu, b, owner);
                int kp = !sup;
                if (t == 0) g_keep[i] = kp;
                if (kp) {
#pragma unroll
                    for (int j = 0; j < 6; ++j) remv[j] |= row[r][j];
                }
                const int ni = i + 8;
                if (ni < PRE_NMS) {
#pragma unroll
                    for (int j = 0; j < 6; ++j) {
                        int w = j * 32 + t;
                        row[r][j] = (w < NWORDS) ? g_mask[ni * NWORDS + w] : 0u;
                    }
                }
            }
        }
    }
}

// ---------------- 12: compact kept boxes into output ------------------------
__global__ void __launch_bounds__(256) out_k(float* __restrict__ out) {
    __shared__ int pre[257];
    const int t = threadIdx.x;
    const int base = t * 24;
    int s = 0;
    for (int k = 0; k < 24; ++k) {
        int i = base + k;
        if (i < PRE_NMS && g_keep[i]) s++;
    }
    pre[t + 1] = s;
    if (t == 0) pre[0] = 0;
    __syncthreads();
    if (t == 0)
        for (int k = 1; k <= 256; ++k) pre[k] += pre[k - 1];
    __syncthreads();
    int rank = pre[t];
    for (int k = 0; k < 24; ++k) {
        int i = base + k;
        if (i < PRE_NMS && g_keep[i]) {
            if (rank < POST_NMS) {
                float4 b = g_props[i];
                out[rank * 4 + 0] = b.x;
                out[rank * 4 + 1] = b.y;
                out[rank * 4 + 2] = b.z;
                out[rank * 4 + 3] = b.w;
            }
            rank++;
        }
    }
}

// ---------------- launcher ---------------------------------------------------
extern "C" void kernel_launch(void* const* d_in, const int* in_sizes, int n_in,
                              void* d_out, int out_size) {
    const float* feature = (const float*)d_in[0];
    const float* w1   = (const float*)d_in[1];
    const float* b1   = (const float*)d_in[2];
    const float* wcls = (const float*)d_in[3];
    const float* bcls = (const float*)d_in[4];
    const float* wreg = (const float*)d_in[5];
    const float* breg = (const float*)d_in[6];
    const int*   imh  = (const int*)d_in[7];
    const int*   imw  = (const int*)d_in[8];
    float* out = (float*)d_out;

    cudaFuncSetAttribute(sort_k, cudaFuncAttributeMaxDynamicSharedMemorySize,
                         CAND_CAP * 8);

    zero_k<<<256, 256>>>(out);
    transw_k<<<(256 * 2304 + 255) / 256, 256>>>(w1);
    conv3x3_k<<<dim3(5, 100, 2), 256>>>(feature, b1);
    heads_k<<<(NPIX + 255) / 256, 128>>>(wcls, bcls, wreg, breg);
    scan1_k<<<1, 256>>>();
    hist2_k<<<(NANCH + 255) / 256, 256>>>();
    scan2_k<<<1, 256>>>();
    compact_k<<<(NANCH + 255) / 256, 256>>>();
    sort_k<<<1, 1024, CAND_CAP * 8>>>();
    decode_k<<<(NBOX_PAD + 255) / 256, 256>>>(imh, imw);
    iou_k<<<dim3(NWORDS, (PRE_NMS + 255) / 256), 256>>>();
    nmsred_k<<<1, 32>>>();
    out_k<<<1, 256>>>(out);
}

// round 7
// speedup vs baseline: 1.9126x; 1.2397x over previous
#include <cuda_runtime.h>
#include <cstdint>

#define HH 200
#define WW 272
#define NPIX 54400
#define NANCH 489600
#define PRE_NMS 6000
#define NWORDS 188
#define NBOX_PAD 6016
#define POST_NMS 1000
#define CAND_CAP 8192

typedef unsigned long long ull;

// ---------------- scratch ----------------------------------------------------
__device__ float        g_x[256 * NPIX];
__device__ float        g_wt[2304 * 256];
__device__ unsigned     g_key[NANCH];
__device__ float4       g_off4[NANCH];
__device__ int          g_hist[65536];
__device__ int          g_hist2[65536];
__device__ int          g_B, g_need;
__device__ unsigned     g_T;
__device__ int          g_cnt;
__device__ unsigned long long g_cand[CAND_CAP];
__device__ int          g_sel[PRE_NMS];
__device__ float4       g_props[NBOX_PAD];
__device__ unsigned     g_invalid[NWORDS];
__device__ unsigned     g_mask[PRE_NMS * NWORDS];
__device__ int          g_keep[PRE_NMS];

__device__ __constant__ float c_aw[9] = {
    45.254833995939045f, 32.f, 22.627416997969522f,
    90.50966799187809f,  64.f, 45.254833995939045f,
    181.01933598375618f, 128.f, 90.50966799187809f};
__device__ __constant__ float c_ah[9] = {
    22.627416997969522f, 32.f, 45.254833995939045f,
    45.254833995939045f, 64.f, 90.50966799187809f,
    90.50966799187809f,  128.f, 181.01933598375618f};

__device__ __forceinline__ unsigned fkey(float f) {
    unsigned u = __float_as_uint(f);
    return (u & 0x80000000u) ? ~u : (u | 0x80000000u);
}

// ---------------- f32x2 packed helpers (SASS FFMA2) --------------------------
__device__ __forceinline__ void fma2(ull& acc, ull x, ull w) {
    asm("fma.rn.f32x2 %0, %1, %2, %0;" : "+l"(acc) : "l"(x), "l"(w));
}
__device__ __forceinline__ ull pack2(float lo, float hi) {
    ull d;
    asm("mov.b64 %0, {%1, %2};" : "=l"(d) : "f"(lo), "f"(hi));
    return d;
}
__device__ __forceinline__ void unpack2(float& lo, float& hi, ull v) {
    asm("mov.b64 {%0, %1}, %2;" : "=f"(lo), "=f"(hi) : "l"(v));
}

// ---------------- 0: init (weight transpose + zero scratch + zero out) -------
__global__ void init_k(const float* __restrict__ w1, float* __restrict__ out) {
    int i = blockIdx.x * 256 + threadIdx.x;
    if (i < 256 * 2304) {
        int oc = i / 2304, r = i % 2304;
        g_wt[r * 256 + oc] = w1[i];
    }
    if (i < 65536) { g_hist[i] = 0; g_hist2[i] = 0; }
    if (i < PRE_NMS) g_keep[i] = 0;
    if (i == 0) g_cnt = 0;
    if (i < NWORDS) g_invalid[i] = 0;
    if (i < POST_NMS * 4) out[i] = 0.f;
}

// ---------------- 1: 3x3 conv 256->256 + bias + relu (FFMA2) ----------------
// 900 blocks of 256 threads:
//   blocks [0,800):  main tile 128 oc x 64 px x 2 rows, x in [0,256) (no waste)
//   blocks [800,900): narrow tile 128 oc x 16 px x 4 rows, x in [256,272)
// Per-output FMA order is (icb, ic, ky, kx) sequential in BOTH paths —
// bit-identical to the passing round-1/4/5/6 kernels.
__global__ void __launch_bounds__(256) conv3x3_k(const float* __restrict__ f,
                                                 const float* __restrict__ b1) {
    __shared__ __align__(16) float sw[8][9][128];    // 8 ic x 9 taps x 128 oc
    __shared__ __align__(16) float sxu[2176];        // main: [8][4][68]; narrow: [8][6][20]
    const int tid = threadIdx.x;
    const int idx = blockIdx.x;

    if (idx < 800) {
        // ================= main path =================
        float (*sx)[4][68] = (float(*)[4][68])sxu;
        const int bz = idx / 400;
        const int rr = idx % 400;
        const int by = rr >> 2, bx = rr & 3;
        const int x0  = bx * 64;
        const int y0  = by * 2;
        const int oc0 = bz * 128;
        const int tx  = tid & 15;
        const int ty  = tid >> 4;
        const int px0 = tx * 4;
        const int ocl = ty * 8;

        ull acc2[4][2][4];
#pragma unroll
        for (int op = 0; op < 4; ++op)
#pragma unroll
            for (int yy = 0; yy < 2; ++yy)
#pragma unroll
                for (int p = 0; p < 4; ++p) acc2[op][yy][p] = 0ULL;

        for (int icb = 0; icb < 32; ++icb) {
            const int ic0 = icb * 8;
            for (int l = tid; l < 8 * 4 * 68; l += 256) {
                int c = l % 68;
                int rest = l / 68;
                int r = rest & 3, ic = rest >> 2;
                int gx = x0 - 1 + c;                 // <= 256 < WW always
                int gy = y0 - 1 + r;
                float v = 0.f;
                if (c < 66 && gx >= 0 && gy >= 0 && gy < HH)
                    v = f[(ic0 + ic) * NPIX + gy * WW + gx];
                sx[ic][r][c] = v;
            }
            for (int l = tid; l < 8 * 9 * 128; l += 256) {
                int oc = l & 127;
                int rk = l >> 7;
                int ic = rk / 9, k = rk % 9;
                sw[ic][k][oc] = g_wt[((ic0 + ic) * 9 + k) * 256 + oc0 + oc];
            }
            __syncthreads();
#pragma unroll 2
            for (int ic = 0; ic < 8; ++ic) {
#pragma unroll
                for (int ky = 0; ky < 3; ++ky) {
                    float4 xa0 = *(const float4*)&sx[ic][ky][px0];
                    float2 xb0 = *(const float2*)&sx[ic][ky][px0 + 4];
                    float4 xa1 = *(const float4*)&sx[ic][ky + 1][px0];
                    float2 xb1 = *(const float2*)&sx[ic][ky + 1][px0 + 4];
                    const float xv0[6] = {xa0.x, xa0.y, xa0.z, xa0.w, xb0.x, xb0.y};
                    const float xv1[6] = {xa1.x, xa1.y, xa1.z, xa1.w, xb1.x, xb1.y};
                    ull xp0[6], xp1[6];
#pragma unroll
                    for (int j = 0; j < 6; ++j) {
                        xp0[j] = pack2(xv0[j], xv0[j]);
                        xp1[j] = pack2(xv1[j], xv1[j]);
                    }
#pragma unroll
                    for (int kx = 0; kx < 3; ++kx) {
                        const ull* wp = (const ull*)&sw[ic][ky * 3 + kx][ocl];
                        ull w0 = wp[0], w1 = wp[1], w2 = wp[2], w3 = wp[3];
#pragma unroll
                        for (int p = 0; p < 4; ++p) {
                            fma2(acc2[0][0][p], xp0[kx + p], w0);
                            fma2(acc2[1][0][p], xp0[kx + p], w1);
                            fma2(acc2[2][0][p], xp0[kx + p], w2);
                            fma2(acc2[3][0][p], xp0[kx + p], w3);
                            fma2(acc2[0][1][p], xp1[kx + p], w0);
                            fma2(acc2[1][1][p], xp1[kx + p], w1);
                            fma2(acc2[2][1][p], xp1[kx + p], w2);
                            fma2(acc2[3][1][p], xp1[kx + p], w3);
                        }
                    }
                }
            }
            __syncthreads();
        }
#pragma unroll
        for (int op = 0; op < 4; ++op) {
            int oce = oc0 + ocl + 2 * op;
            float be = b1[oce];
            float bo = b1[oce + 1];
#pragma unroll
            for (int yy = 0; yy < 2; ++yy) {
                int y = y0 + yy;
#pragma unroll
                for (int p = 0; p < 4; ++p) {
                    float ae, ao;
                    unpack2(ae, ao, acc2[op][yy][p]);
                    int gx = x0 + px0 + p;           // < 256 always valid
                    g_x[oce * NPIX + y * WW + gx] = fmaxf(ae + be, 0.f);
                    g_x[(oce + 1) * NPIX + y * WW + gx] = fmaxf(ao + bo, 0.f);
                }
            }
        }
    } else {
        // ================= narrow path (x 256..271) =================
        float (*sx)[6][20] = (float(*)[6][20])sxu;
        const int n  = idx - 800;
        const int bz = n / 50;
        const int by = n % 50;
        const int y0  = by * 4;
        const int oc0 = bz * 128;
        const int tx  = tid & 3;         // 4 px groups of 4
        const int ty  = tid >> 2;        // 64 oc pairs
        const int px0 = tx * 4;          // local px offset (global 256+px0)

        ull acc2[4][4];                  // [row][px], lanes = oc pair
#pragma unroll
        for (int yy = 0; yy < 4; ++yy)
#pragma unroll
            for (int p = 0; p < 4; ++p) acc2[yy][p] = 0ULL;

        for (int icb = 0; icb < 32; ++icb) {
            const int ic0 = icb * 8;
            for (int l = tid; l < 8 * 6 * 20; l += 256) {
                int c = l % 20;
                int rest = l / 20;
                int r = rest % 6, ic = rest / 6;
                int gx = 255 + c;                    // c<17 -> gx<272
                int gy = y0 - 1 + r;
                float v = 0.f;
                if (c < 17 && gy >= 0 && gy < HH)
                    v = f[(ic0 + ic) * NPIX + gy * WW + gx];
                sx[ic][r][c] = v;
            }
            for (int l = tid; l < 8 * 9 * 128; l += 256) {
                int oc = l & 127;
                int rk = l >> 7;
                int ic = rk / 9, k = rk % 9;
                sw[ic][k][oc] = g_wt[((ic0 + ic) * 9 + k) * 256 + oc0 + oc];
            }
            __syncthreads();
#pragma unroll 2
            for (int ic = 0; ic < 8; ++ic) {
#pragma unroll
                for (int ky = 0; ky < 3; ++ky) {
                    ull xp[4][6];
#pragma unroll
                    for (int yy = 0; yy < 4; ++yy) {
                        float4 xa = *(const float4*)&sx[ic][ky + yy][px0];
                        float2 xb = *(const float2*)&sx[ic][ky + yy][px0 + 4];
                        xp[yy][0] = pack2(xa.x, xa.x);
                        xp[yy][1] = pack2(xa.y, xa.y);
                        xp[yy][2] = pack2(xa.z, xa.z);
                        xp[yy][3] = pack2(xa.w, xa.w);
                        xp[yy][4] = pack2(xb.x, xb.x);
                        xp[yy][5] = pack2(xb.y, xb.y);
                    }
#pragma unroll
                    for (int kx = 0; kx < 3; ++kx) {
                        ull w = *(const ull*)&sw[ic][ky * 3 + kx][ty * 2];
#pragma unroll
                        for (int yy = 0; yy < 4; ++yy)
#pragma unroll
                            for (int p = 0; p < 4; ++p)
                                fma2(acc2[yy][p], xp[yy][kx + p], w);
                    }
                }
            }
            __syncthreads();
        }
        {
            int oce = oc0 + ty * 2;
            float be = b1[oce];
            float bo = b1[oce + 1];
#pragma unroll
            for (int yy = 0; yy < 4; ++yy) {
                int y = y0 + yy;
#pragma unroll
                for (int p = 0; p < 4; ++p) {
                    float ae, ao;
                    unpack2(ae, ao, acc2[yy][p]);
                    int gx = 256 + px0 + p;          // 256..271 valid
                    g_x[oce * NPIX + y * WW + gx] = fmaxf(ae + be, 0.f);
                    g_x[(oce + 1) * NPIX + y * WW + gx] = fmaxf(ao + bo, 0.f);
                }
            }
        }
    }
}

// ---------------- 2: 1x1 heads (1 px/thread, float4 weight LDS) -------------
// Per-pixel accumulation statements identical to rounds 4/5/6 (bit-identical).
__global__ void __launch_bounds__(256) heads_k(const float* __restrict__ wcls,
                                               const float* __restrict__ bcls,
                                               const float* __restrict__ wreg,
                                               const float* __restrict__ breg) {
    __shared__ float4 swc[9 * 64];
    __shared__ float4 swr[36 * 64];
    const int t = threadIdx.x;
    for (int l = t; l < 9 * 64; l += 256)  swc[l] = ((const float4*)wcls)[l];
    for (int l = t; l < 36 * 64; l += 256) swr[l] = ((const float4*)wreg)[l];
    __syncthreads();
    const int p = blockIdx.x * 256 + t;
    if (p >= NPIX) return;

    float c0[9], r0[36];
#pragma unroll
    for (int a = 0; a < 9; ++a)  c0[a] = bcls[a];
#pragma unroll
    for (int o = 0; o < 36; ++o) r0[o] = breg[o];

    for (int icq = 0; icq < 64; ++icq) {
        const int ic = icq * 4;
        float xa0 = g_x[ic * NPIX + p];
        float xa1 = g_x[(ic + 1) * NPIX + p];
        float xa2 = g_x[(ic + 2) * NPIX + p];
        float xa3 = g_x[(ic + 3) * NPIX + p];
#pragma unroll
        for (int a = 0; a < 9; ++a) {
            float4 w = swc[a * 64 + icq];
            c0[a] += xa0 * w.x + xa1 * w.y;
            c0[a] += xa2 * w.z + xa3 * w.w;
        }
#pragma unroll
        for (int o = 0; o < 36; ++o) {
            float4 w = swr[o * 64 + icq];
            r0[o] += xa0 * w.x + xa1 * w.y;
            r0[o] += xa2 * w.z + xa3 * w.w;
        }
    }
#pragma unroll
    for (int a = 0; a < 9; ++a) {
        int n = p * 9 + a;
        unsigned k = fkey(c0[a]);
        g_key[n] = k;
        atomicAdd(&g_hist[k >> 16], 1);
        g_off4[n] = make_float4(r0[4 * a], r0[4 * a + 1], r0[4 * a + 2],
                                r0[4 * a + 3]);
    }
}

// ---------------- 3..10: selection / sort / decode / NMS ---------------------
__global__ void scan1_k() {
    __shared__ int cs[256];
    int t = threadIdx.x;
    int s = 0;
    for (int k = 0; k < 256; ++k) s += g_hist[t * 256 + k];
    cs[t] = s;
    __syncthreads();
    if (t == 0) {
        long long S = 0;
        int tc = 0;
        for (int cch = 255; cch >= 0; --cch) {
            if (S + cs[cch] >= PRE_NMS) { tc = cch; break; }
            S += cs[cch];
        }
        for (int b = tc * 256 + 255;; --b) {
            if (S + g_hist[b] >= PRE_NMS || b == tc * 256) {
                g_B = b;
                g_need = PRE_NMS - (int)S;
                break;
            }
            S += g_hist[b];
        }
    }
}

__global__ void hist2_k() {
    int i = blockIdx.x * 256 + threadIdx.x;
    if (i < NANCH) {
        unsigned k = g_key[i];
        if ((int)(k >> 16) == g_B) atomicAdd(&g_hist2[k & 0xFFFFu], 1);
    }
}

__global__ void scan2_k() {
    __shared__ int cs[256];
    int t = threadIdx.x;
    int s = 0;
    for (int k = 0; k < 256; ++k) s += g_hist2[t * 256 + k];
    cs[t] = s;
    __syncthreads();
    if (t == 0) {
        int need = g_need;
        long long S = 0;
        int tc = 0;
        for (int cch = 255; cch >= 0; --cch) {
            if (S + cs[cch] >= need) { tc = cch; break; }
            S += cs[cch];
        }
        int L = tc * 256;
        for (int b = tc * 256 + 255;; --b) {
            if (S + g_hist2[b] >= need || b == tc * 256) { L = b; break; }
            S += g_hist2[b];
        }
        g_T = ((unsigned)g_B << 16) | (unsigned)L;
    }
}

__global__ void compact_k() {
    int i = blockIdx.x * 256 + threadIdx.x;
    if (i < NANCH) {
        unsigned k = g_key[i];
        if (k >= g_T) {
            int pos = atomicAdd(&g_cnt, 1);
            if (pos < CAND_CAP)
                g_cand[pos] = ((unsigned long long)k << 32) |
                              (unsigned long long)(0xFFFFFFFFu - (unsigned)i);
        }
    }
}

__global__ void __launch_bounds__(1024) sort_k() {
    extern __shared__ unsigned long long s[];
    int t = threadIdx.x;
    int cnt = g_cnt;
    if (cnt > CAND_CAP) cnt = CAND_CAP;
    for (int l = t; l < CAND_CAP; l += 1024)
        s[l] = (l < cnt) ? g_cand[l] : 0ULL;
    __syncthreads();
    for (int k = 2; k <= CAND_CAP; k <<= 1) {
        for (int j = k >> 1; j > 0; j >>= 1) {
            for (int idx = t; idx < CAND_CAP; idx += 1024) {
                int ixj = idx ^ j;
                if (ixj > idx) {
                    unsigned long long va = s[idx], vb = s[ixj];
                    bool up = ((idx & k) == 0);
                    if (up ? (va < vb) : (va > vb)) { s[idx] = vb; s[ixj] = va; }
                }
            }
            __syncthreads();
        }
    }
    for (int l = t; l < PRE_NMS; l += 1024)
        g_sel[l] = (int)(0xFFFFFFFFu - (unsigned)s[l]);
}

__global__ void decode_k(const int* __restrict__ imh, const int* __restrict__ imw) {
    int i = blockIdx.x * 256 + threadIdx.x;
    if (i >= NBOX_PAD) return;
    if (i >= PRE_NMS) { g_props[i] = make_float4(0.f, 0.f, 0.f, 0.f); return; }
    int n = g_sel[i];
    int a = n % 9, p = n / 9;
    int x = p % WW, y = p / WW;
    float cx0 = (x + 0.5f) * 4.f, cy0 = (y + 0.5f) * 4.f;
    float x1a = cx0 - 0.5f * c_aw[a], x2a = cx0 + 0.5f * c_aw[a];
    float y1a = cy0 - 0.5f * c_ah[a], y2a = cy0 + 0.5f * c_ah[a];
    float wa = x2a - x1a, ha = y2a - y1a;
    float cxa = x1a + 0.5f * wa, cya = y1a + 0.5f * ha;
    float4 d = g_off4[n];
    float cx = d.x * wa + cxa, cy = d.y * ha + cya;
    float w = expf(d.z) * wa, h = expf(d.w) * ha;
    float W = (float)imw[0], H = (float)imh[0];
    float x1 = fminf(fmaxf(cx - 0.5f * w, 0.f), W);
    float y1 = fminf(fmaxf(cy - 0.5f * h, 0.f), H);
    float x2 = fminf(fmaxf(cx + 0.5f * w, 0.f), W);
    float y2 = fminf(fmaxf(cy + 0.5f * h, 0.f), H);
    g_props[i] = make_float4(x1, y1, x2, y2);
    bool valid = ((x2 - x1) >= 1.f) && ((y2 - y1) >= 1.f);
    if (!valid) atomicOr(&g_invalid[i >> 5], 1u << (i & 31));
}

// IoU bitmask — upper-triangular words only (bits for cols < row are never
// read by the serial reduce: row i is OR'd into remv at iteration i, and
// remv bit k is only read at iteration k > i).
__global__ void __launch_bounds__(256) iou_k() {
    __shared__ float4 jb[32];
    const int wcol = blockIdx.x;
    if (wcol < (int)(blockIdx.y << 3)) return;   // whole block exits: safe
    const int i = blockIdx.y * 256 + threadIdx.x;
    if (threadIdx.x < 32) jb[threadIdx.x] = g_props[wcol * 32 + threadIdx.x];
    __syncthreads();
    if (i >= PRE_NMS) return;
    float4 a = g_props[i];
    float areaA = (a.z - a.x) * (a.w - a.y);
    unsigned m = 0;
#pragma unroll 4
    for (int k = 0; k < 32; ++k) {
        float4 b = jb[k];
        float areaB = (b.z - b.x) * (b.w - b.y);
        float lx = fmaxf(a.x, b.x), ly = fmaxf(a.y, b.y);
        float rx = fminf(a.z, b.z), ry = fminf(a.w, b.w);
        float iw = fmaxf(rx - lx, 0.f), ih = fmaxf(ry - ly, 0.f);
        float inter = iw * ih;
        float iou = __fdiv_rn(inter, areaA + areaB - inter + 1e-9f);
        if (iou > 0.7f) m |= (1u << k);
    }
    g_mask[i * NWORDS + wcol] = m;
}

// single-warp register-resident NMS reduce with early exit at POST_NMS kept
// (later decisions cannot affect the output; g_keep is pre-zeroed).
__global__ void __launch_bounds__(32) nmsred_k() {
    const int t = threadIdx.x;
    unsigned remv[6];
#pragma unroll
    for (int j = 0; j < 6; ++j) {
        int w = j * 32 + t;
        remv[j] = (w < NWORDS) ? g_invalid[w] : 0u;
    }
    unsigned row[8][6];
#pragma unroll
    for (int r = 0; r < 8; ++r)
#pragma unroll
        for (int j = 0; j < 6; ++j) {
            int w = j * 32 + t;
            row[r][j] = (w < NWORDS) ? g_mask[r * NWORDS + w] : 0u;
        }
    int cnt = 0;
#pragma unroll
    for (int slot = 0; slot < 6; ++slot) {
        const int iend = (slot + 1) * 1024 < PRE_NMS ? (slot + 1) * 1024 : PRE_NMS;
        for (int ib = slot * 1024; ib < iend; ib += 8) {
#pragma unroll
            for (int r = 0; r < 8; ++r) {
                const int i = ib + r;
                const int wi = i >> 5;
                const int owner = wi & 31;
                unsigned b = (remv[slot] >> (i & 31)) & 1u;
                unsigned sup = __shfl_sync(0xFFFFFFFFu, b, owner);
                int kp = !sup;
                if (t == 0) g_keep[i] = kp;
                cnt += kp;
                if (kp) {
#pragma unroll
                    for (int j = 0; j < 6; ++j) remv[j] |= row[r][j];
                }
                if (cnt >= POST_NMS) return;
                const int ni = i + 8;
                if (ni < PRE_NMS) {
#pragma unroll
                    for (int j = 0; j < 6; ++j) {
                        int w = j * 32 + t;
                        row[r][j] = (w < NWORDS) ? g_mask[ni * NWORDS + w] : 0u;
                    }
                }
            }
        }
    }
}

__global__ void __launch_bounds__(256) out_k(float* __restrict__ out) {
    __shared__ int pre[257];
    const int t = threadIdx.x;
    const int base = t * 24;
    int s = 0;
    for (int k = 0; k < 24; ++k) {
        int i = base + k;
        if (i < PRE_NMS && g_keep[i]) s++;
    }
    pre[t + 1] = s;
    if (t == 0) pre[0] = 0;
    __syncthreads();
    if (t == 0)
        for (int k = 1; k <= 256; ++k) pre[k] += pre[k - 1];
    __syncthreads();
    int rank = pre[t];
    for (int k = 0; k < 24; ++k) {
        int i = base + k;
        if (i < PRE_NMS && g_keep[i]) {
            if (rank < POST_NMS) {
                float4 b = g_props[i];
                out[rank * 4 + 0] = b.x;
                out[rank * 4 + 1] = b.y;
                out[rank * 4 + 2] = b.z;
                out[rank * 4 + 3] = b.w;
            }
            rank++;
        }
    }
}

// ---------------- launcher ---------------------------------------------------
extern "C" void kernel_launch(void* const* d_in, const int* in_sizes, int n_in,
                              void* d_out, int out_size) {
    const float* feature = (const float*)d_in[0];
    const float* w1   = (const float*)d_in[1];
    const float* b1   = (const float*)d_in[2];
    const float* wcls = (const float*)d_in[3];
    const float* bcls = (const float*)d_in[4];
    const float* wreg = (const float*)d_in[5];
    const float* breg = (const float*)d_in[6];
    const int*   imh  = (const int*)d_in[7];
    const int*   imw  = (const int*)d_in[8];
    float* out = (float*)d_out;

    cudaFuncSetAttribute(sort_k, cudaFuncAttributeMaxDynamicSharedMemorySize,
                         CAND_CAP * 8);

    init_k<<<2304, 256>>>(w1, out);
    conv3x3_k<<<900, 256>>>(feature, b1);
    heads_k<<<(NPIX + 255) / 256, 256>>>(wcls, bcls, wreg, breg);
    scan1_k<<<1, 256>>>();
    hist2_k<<<(NANCH + 255) / 256, 256>>>();
    scan2_k<<<1, 256>>>();
    compact_k<<<(NANCH + 255) / 256, 256>>>();
    sort_k<<<1, 1024, CAND_CAP * 8>>>();
    decode_k<<<(NBOX_PAD + 255) / 256, 256>>>(imh, imw);
    iou_k<<<dim3(NWORDS, (PRE_NMS + 255) / 256), 256>>>();
    nmsred_k<<<1, 32>>>();
    out_k<<<1, 256>>>(out);
}

// round 8
// speedup vs baseline: 2.0634x; 1.0788x over previous
#include <cuda_runtime.h>
#include <cstdint>

#define HH 200
#define WW 272
#define NPIX 54400
#define NANCH 489600
#define PRE_NMS 6000
#define NWORDS 188
#define NBOX_PAD 6016
#define POST_NMS 1000
#define CAND_CAP 8192

typedef unsigned long long ull;

// ---------------- scratch ----------------------------------------------------
__device__ float        g_x[256 * NPIX];
__device__ float        g_wt[2304 * 256];
__device__ unsigned     g_key[NANCH];
__device__ float4       g_off4[NANCH];
__device__ int          g_hist[65536];
__device__ int          g_hist2[65536];
__device__ int          g_B, g_need;
__device__ unsigned     g_T;
__device__ int          g_cnt;
__device__ unsigned long long g_cand[CAND_CAP];
__device__ float4       g_props[NBOX_PAD];
__device__ unsigned     g_invalid[NWORDS];
__device__ unsigned     g_mask[PRE_NMS * NWORDS];
__device__ int          g_keep[PRE_NMS];

__device__ __constant__ float c_aw[9] = {
    45.254833995939045f, 32.f, 22.627416997969522f,
    90.50966799187809f,  64.f, 45.254833995939045f,
    181.01933598375618f, 128.f, 90.50966799187809f};
__device__ __constant__ float c_ah[9] = {
    22.627416997969522f, 32.f, 45.254833995939045f,
    45.254833995939045f, 64.f, 90.50966799187809f,
    90.50966799187809f,  128.f, 181.01933598375618f};

__device__ __forceinline__ unsigned fkey(float f) {
    unsigned u = __float_as_uint(f);
    return (u & 0x80000000u) ? ~u : (u | 0x80000000u);
}

// ---------------- f32x2 packed helpers (SASS FFMA2) --------------------------
__device__ __forceinline__ void fma2(ull& acc, ull x, ull w) {
    asm("fma.rn.f32x2 %0, %1, %2, %0;" : "+l"(acc) : "l"(x), "l"(w));
}
__device__ __forceinline__ ull pack2(float lo, float hi) {
    ull d;
    asm("mov.b64 %0, {%1, %2};" : "=l"(d) : "f"(lo), "f"(hi));
    return d;
}
__device__ __forceinline__ void unpack2(float& lo, float& hi, ull v) {
    asm("mov.b64 {%0, %1}, %2;" : "=f"(lo), "=f"(hi) : "l"(v));
}

// ---------------- 0: init (weight transpose + zero scratch + zero out) -------
__global__ void init_k(const float* __restrict__ w1, float* __restrict__ out) {
    int i = blockIdx.x * 256 + threadIdx.x;
    if (i < 256 * 2304) {
        int oc = i / 2304, r = i % 2304;
        g_wt[r * 256 + oc] = w1[i];
    }
    if (i < 65536) { g_hist[i] = 0; g_hist2[i] = 0; }
    if (i < PRE_NMS) g_keep[i] = 0;
    if (i == 0) g_cnt = 0;
    if (i < NWORDS) g_invalid[i] = 0;
    if (i < POST_NMS * 4) out[i] = 0.f;
}

// ---------------- 1: 3x3 conv 256->256 + bias + relu (FFMA2) ----------------
// 900 blocks: [0,800) main 128oc x 64px x 2rows (x<256, no waste);
// [800,900) narrow 128oc x 16px x 4rows (x 256..271).
// Per-output FMA order (icb, ic, ky, kx) sequential — bit-identical.
__global__ void __launch_bounds__(256) conv3x3_k(const float* __restrict__ f,
                                                 const float* __restrict__ b1) {
    __shared__ __align__(16) float sw[8][9][128];
    __shared__ __align__(16) float sxu[2176];
    const int tid = threadIdx.x;
    const int idx = blockIdx.x;

    if (idx < 800) {
        float (*sx)[4][68] = (float(*)[4][68])sxu;
        const int bz = idx / 400;
        const int rr = idx % 400;
        const int by = rr >> 2, bx = rr & 3;
        const int x0  = bx * 64;
        const int y0  = by * 2;
        const int oc0 = bz * 128;
        const int tx  = tid & 15;
        const int ty  = tid >> 4;
        const int px0 = tx * 4;
        const int ocl = ty * 8;

        ull acc2[4][2][4];
#pragma unroll
        for (int op = 0; op < 4; ++op)
#pragma unroll
            for (int yy = 0; yy < 2; ++yy)
#pragma unroll
                for (int p = 0; p < 4; ++p) acc2[op][yy][p] = 0ULL;

        for (int icb = 0; icb < 32; ++icb) {
            const int ic0 = icb * 8;
            for (int l = tid; l < 8 * 4 * 68; l += 256) {
                int c = l % 68;
                int rest = l / 68;
                int r = rest & 3, ic = rest >> 2;
                int gx = x0 - 1 + c;
                int gy = y0 - 1 + r;
                float v = 0.f;
                if (c < 66 && gx >= 0 && gy >= 0 && gy < HH)
                    v = f[(ic0 + ic) * NPIX + gy * WW + gx];
                sx[ic][r][c] = v;
            }
            for (int l = tid; l < 8 * 9 * 128; l += 256) {
                int oc = l & 127;
                int rk = l >> 7;
                int ic = rk / 9, k = rk % 9;
                sw[ic][k][oc] = g_wt[((ic0 + ic) * 9 + k) * 256 + oc0 + oc];
            }
            __syncthreads();
#pragma unroll 2
            for (int ic = 0; ic < 8; ++ic) {
#pragma unroll
                for (int ky = 0; ky < 3; ++ky) {
                    float4 xa0 = *(const float4*)&sx[ic][ky][px0];
                    float2 xb0 = *(const float2*)&sx[ic][ky][px0 + 4];
                    float4 xa1 = *(const float4*)&sx[ic][ky + 1][px0];
                    float2 xb1 = *(const float2*)&sx[ic][ky + 1][px0 + 4];
                    const float xv0[6] = {xa0.x, xa0.y, xa0.z, xa0.w, xb0.x, xb0.y};
                    const float xv1[6] = {xa1.x, xa1.y, xa1.z, xa1.w, xb1.x, xb1.y};
                    ull xp0[6], xp1[6];
#pragma unroll
                    for (int j = 0; j < 6; ++j) {
                        xp0[j] = pack2(xv0[j], xv0[j]);
                        xp1[j] = pack2(xv1[j], xv1[j]);
                    }
#pragma unroll
                    for (int kx = 0; kx < 3; ++kx) {
                        const ull* wp = (const ull*)&sw[ic][ky * 3 + kx][ocl];
                        ull w0 = wp[0], w1 = wp[1], w2 = wp[2], w3 = wp[3];
#pragma unroll
                        for (int p = 0; p < 4; ++p) {
                            fma2(acc2[0][0][p], xp0[kx + p], w0);
                            fma2(acc2[1][0][p], xp0[kx + p], w1);
                            fma2(acc2[2][0][p], xp0[kx + p], w2);
                            fma2(acc2[3][0][p], xp0[kx + p], w3);
                            fma2(acc2[0][1][p], xp1[kx + p], w0);
                            fma2(acc2[1][1][p], xp1[kx + p], w1);
                            fma2(acc2[2][1][p], xp1[kx + p], w2);
                            fma2(acc2[3][1][p], xp1[kx + p], w3);
                        }
                    }
                }
            }
            __syncthreads();
        }
#pragma unroll
        for (int op = 0; op < 4; ++op) {
            int oce = oc0 + ocl + 2 * op;
            float be = b1[oce];
            float bo = b1[oce + 1];
#pragma unroll
            for (int yy = 0; yy < 2; ++yy) {
                int y = y0 + yy;
#pragma unroll
                for (int p = 0; p < 4; ++p) {
                    float ae, ao;
                    unpack2(ae, ao, acc2[op][yy][p]);
                    int gx = x0 + px0 + p;
                    g_x[oce * NPIX + y * WW + gx] = fmaxf(ae + be, 0.f);
                    g_x[(oce + 1) * NPIX + y * WW + gx] = fmaxf(ao + bo, 0.f);
                }
            }
        }
    } else {
        float (*sx)[6][20] = (float(*)[6][20])sxu;
        const int n  = idx - 800;
        const int bz = n / 50;
        const int by = n % 50;
        const int y0  = by * 4;
        const int oc0 = bz * 128;
        const int tx  = tid & 3;
        const int ty  = tid >> 2;
        const int px0 = tx * 4;

        ull acc2[4][4];
#pragma unroll
        for (int yy = 0; yy < 4; ++yy)
#pragma unroll
            for (int p = 0; p < 4; ++p) acc2[yy][p] = 0ULL;

        for (int icb = 0; icb < 32; ++icb) {
            const int ic0 = icb * 8;
            for (int l = tid; l < 8 * 6 * 20; l += 256) {
                int c = l % 20;
                int rest = l / 20;
                int r = rest % 6, ic = rest / 6;
                int gx = 255 + c;
                int gy = y0 - 1 + r;
                float v = 0.f;
                if (c < 17 && gy >= 0 && gy < HH)
                    v = f[(ic0 + ic) * NPIX + gy * WW + gx];
                sx[ic][r][c] = v;
            }
            for (int l = tid; l < 8 * 9 * 128; l += 256) {
                int oc = l & 127;
                int rk = l >> 7;
                int ic = rk / 9, k = rk % 9;
                sw[ic][k][oc] = g_wt[((ic0 + ic) * 9 + k) * 256 + oc0 + oc];
            }
            __syncthreads();
#pragma unroll 2
            for (int ic = 0; ic < 8; ++ic) {
#pragma unroll
                for (int ky = 0; ky < 3; ++ky) {
                    ull xp[4][6];
#pragma unroll
                    for (int yy = 0; yy < 4; ++yy) {
                        float4 xa = *(const float4*)&sx[ic][ky + yy][px0];
                        float2 xb = *(const float2*)&sx[ic][ky + yy][px0 + 4];
                        xp[yy][0] = pack2(xa.x, xa.x);
                        xp[yy][1] = pack2(xa.y, xa.y);
                        xp[yy][2] = pack2(xa.z, xa.z);
                        xp[yy][3] = pack2(xa.w, xa.w);
                        xp[yy][4] = pack2(xb.x, xb.x);
                        xp[yy][5] = pack2(xb.y, xb.y);
                    }
#pragma unroll
                    for (int kx = 0; kx < 3; ++kx) {
                        ull w = *(const ull*)&sw[ic][ky * 3 + kx][ty * 2];
#pragma unroll
                        for (int yy = 0; yy < 4; ++yy)
#pragma unroll
                            for (int p = 0; p < 4; ++p)
                                fma2(acc2[yy][p], xp[yy][kx + p], w);
                    }
                }
            }
            __syncthreads();
        }
        {
            int oce = oc0 + ty * 2;
            float be = b1[oce];
            float bo = b1[oce + 1];
#pragma unroll
            for (int yy = 0; yy < 4; ++yy) {
                int y = y0 + yy;
#pragma unroll
                for (int p = 0; p < 4; ++p) {
                    float ae, ao;
                    unpack2(ae, ao, acc2[yy][p]);
                    int gx = 256 + px0 + p;
                    g_x[oce * NPIX + y * WW + gx] = fmaxf(ae + be, 0.f);
                    g_x[(oce + 1) * NPIX + y * WW + gx] = fmaxf(ao + bo, 0.f);
                }
            }
        }
    }
}

// ---------------- 2: 1x1 heads (1 px/thread) ---------------------------------
__global__ void __launch_bounds__(256) heads_k(const float* __restrict__ wcls,
                                               const float* __restrict__ bcls,
                                               const float* __restrict__ wreg,
                                               const float* __restrict__ breg) {
    __shared__ float4 swc[9 * 64];
    __shared__ float4 swr[36 * 64];
    const int t = threadIdx.x;
    for (int l = t; l < 9 * 64; l += 256)  swc[l] = ((const float4*)wcls)[l];
    for (int l = t; l < 36 * 64; l += 256) swr[l] = ((const float4*)wreg)[l];
    __syncthreads();
    const int p = blockIdx.x * 256 + t;
    if (p >= NPIX) return;

    float c0[9], r0[36];
#pragma unroll
    for (int a = 0; a < 9; ++a)  c0[a] = bcls[a];
#pragma unroll
    for (int o = 0; o < 36; ++o) r0[o] = breg[o];

    for (int icq = 0; icq < 64; ++icq) {
        const int ic = icq * 4;
        float xa0 = g_x[ic * NPIX + p];
        float xa1 = g_x[(ic + 1) * NPIX + p];
        float xa2 = g_x[(ic + 2) * NPIX + p];
        float xa3 = g_x[(ic + 3) * NPIX + p];
#pragma unroll
        for (int a = 0; a < 9; ++a) {
            float4 w = swc[a * 64 + icq];
            c0[a] += xa0 * w.x + xa1 * w.y;
            c0[a] += xa2 * w.z + xa3 * w.w;
        }
#pragma unroll
        for (int o = 0; o < 36; ++o) {
            float4 w = swr[o * 64 + icq];
            r0[o] += xa0 * w.x + xa1 * w.y;
            r0[o] += xa2 * w.z + xa3 * w.w;
        }
    }
#pragma unroll
    for (int a = 0; a < 9; ++a) {
        int n = p * 9 + a;
        unsigned k = fkey(c0[a]);
        g_key[n] = k;
        atomicAdd(&g_hist[k >> 16], 1);
        g_off4[n] = make_float4(r0[4 * a], r0[4 * a + 1], r0[4 * a + 2],
                                r0[4 * a + 3]);
    }
}

// ---------------- 3: boundary bin via parallel suffix scans ------------------
// Reproduces the serial descending scan exactly: stop bin = max b with
// suffix_sum(b) >= target (predicate is monotone in b).
__global__ void scan1_k() {
    __shared__ int suf1[256];
    __shared__ int suf2[256];
    __shared__ int s_tc, s_b;
    const int t = threadIdx.x;
    int s = 0;
    const int4* hp = (const int4*)&g_hist[t * 256];
#pragma unroll 8
    for (int k = 0; k < 64; ++k) { int4 v = hp[k]; s += v.x + v.y + v.z + v.w; }
    if (t == 0) { s_tc = -1; s_b = -1; }
    suf1[t] = s;
    __syncthreads();
    for (int off = 1; off < 256; off <<= 1) {
        int v = (t + off < 256) ? suf1[t + off] : 0;
        __syncthreads();
        suf1[t] += v;
        __syncthreads();
    }
    if (suf1[t] >= PRE_NMS) atomicMax(&s_tc, t);
    __syncthreads();
    const int tc = s_tc;
    const int S1 = (tc + 1 < 256) ? suf1[tc + 1] : 0;
    suf2[t] = g_hist[tc * 256 + t];
    __syncthreads();
    for (int off = 1; off < 256; off <<= 1) {
        int v = (t + off < 256) ? suf2[t + off] : 0;
        __syncthreads();
        suf2[t] += v;
        __syncthreads();
    }
    if (S1 + suf2[t] >= PRE_NMS) atomicMax(&s_b, t);
    __syncthreads();
    if (t == 0) {
        int b = s_b;                              // >= 0 guaranteed
        int S = S1 + ((b + 1 < 256) ? suf2[b + 1] : 0);
        g_B = tc * 256 + b;
        g_need = PRE_NMS - S;
    }
}

__global__ void hist2_k() {
    int i = blockIdx.x * 256 + threadIdx.x;
    if (i < NANCH) {
        unsigned k = g_key[i];
        if ((int)(k >> 16) == g_B) atomicAdd(&g_hist2[k & 0xFFFFu], 1);
    }
}

__global__ void scan2_k() {
    __shared__ int suf1[256];
    __shared__ int suf2[256];
    __shared__ int s_tc, s_b;
    const int t = threadIdx.x;
    const int need = g_need;
    int s = 0;
    const int4* hp = (const int4*)&g_hist2[t * 256];
#pragma unroll 8
    for (int k = 0; k < 64; ++k) { int4 v = hp[k]; s += v.x + v.y + v.z + v.w; }
    if (t == 0) { s_tc = -1; s_b = -1; }
    suf1[t] = s;
    __syncthreads();
    for (int off = 1; off < 256; off <<= 1) {
        int v = (t + off < 256) ? suf1[t + off] : 0;
        __syncthreads();
        suf1[t] += v;
        __syncthreads();
    }
    if (suf1[t] >= need) atomicMax(&s_tc, t);
    __syncthreads();
    const int tc = s_tc;
    const int S1 = (tc + 1 < 256) ? suf1[tc + 1] : 0;
    suf2[t] = g_hist2[tc * 256 + t];
    __syncthreads();
    for (int off = 1; off < 256; off <<= 1) {
        int v = (t + off < 256) ? suf2[t + off] : 0;
        __syncthreads();
        suf2[t] += v;
        __syncthreads();
    }
    if (S1 + suf2[t] >= need) atomicMax(&s_b, t);
    __syncthreads();
    if (t == 0) {
        int L = tc * 256 + s_b;
        g_T = ((unsigned)g_B << 16) | (unsigned)L;
    }
}

__global__ void compact_k() {
    int i = blockIdx.x * 256 + threadIdx.x;
    if (i < NANCH) {
        unsigned k = g_key[i];
        if (k >= g_T) {
            int pos = atomicAdd(&g_cnt, 1);
            if (pos < CAND_CAP)
                g_cand[pos] = ((unsigned long long)k << 32) |
                              (unsigned long long)(0xFFFFFFFFu - (unsigned)i);
        }
    }
}

// ---------------- 4: bitonic sort + fused decode/clip/min-size ---------------
__global__ void __launch_bounds__(1024) sortdec_k(const int* __restrict__ imh,
                                                  const int* __restrict__ imw) {
    extern __shared__ unsigned long long s[];
    int t = threadIdx.x;
    int cnt = g_cnt;
    if (cnt > CAND_CAP) cnt = CAND_CAP;
    for (int l = t; l < CAND_CAP; l += 1024)
        s[l] = (l < cnt) ? g_cand[l] : 0ULL;
    __syncthreads();
    for (int k = 2; k <= CAND_CAP; k <<= 1) {
        for (int j = k >> 1; j > 0; j >>= 1) {
            for (int idx = t; idx < CAND_CAP; idx += 1024) {
                int ixj = idx ^ j;
                if (ixj > idx) {
                    unsigned long long va = s[idx], vb = s[ixj];
                    bool up = ((idx & k) == 0);
                    if (up ? (va < vb) : (va > vb)) { s[idx] = vb; s[ixj] = va; }
                }
            }
            __syncthreads();
        }
    }
    // fused decode (exactly the former decode_k math)
    const float W = (float)imw[0], H = (float)imh[0];
    for (int i = t; i < NBOX_PAD; i += 1024) {
        if (i >= PRE_NMS) { g_props[i] = make_float4(0.f, 0.f, 0.f, 0.f); continue; }
        int n = (int)(0xFFFFFFFFu - (unsigned)s[i]);
        int a = n % 9, p = n / 9;
        int x = p % WW, y = p / WW;
        float cx0 = (x + 0.5f) * 4.f, cy0 = (y + 0.5f) * 4.f;
        float x1a = cx0 - 0.5f * c_aw[a], x2a = cx0 + 0.5f * c_aw[a];
        float y1a = cy0 - 0.5f * c_ah[a], y2a = cy0 + 0.5f * c_ah[a];
        float wa = x2a - x1a, ha = y2a - y1a;
        float cxa = x1a + 0.5f * wa, cya = y1a + 0.5f * ha;
        float4 d = g_off4[n];
        float cx = d.x * wa + cxa, cy = d.y * ha + cya;
        float w = expf(d.z) * wa, h = expf(d.w) * ha;
        float x1 = fminf(fmaxf(cx - 0.5f * w, 0.f), W);
        float y1 = fminf(fmaxf(cy - 0.5f * h, 0.f), H);
        float x2 = fminf(fmaxf(cx + 0.5f * w, 0.f), W);
        float y2 = fminf(fmaxf(cy + 0.5f * h, 0.f), H);
        g_props[i] = make_float4(x1, y1, x2, y2);
        bool valid = ((x2 - x1) >= 1.f) && ((y2 - y1) >= 1.f);
        if (!valid) atomicOr(&g_invalid[i >> 5], 1u << (i & 31));
    }
}

// ---------------- 5: IoU bitmask (upper triangle) ----------------------------
__global__ void __launch_bounds__(256) iou_k() {
    __shared__ float4 jb[32];
    const int wcol = blockIdx.x;
    if (wcol < (int)(blockIdx.y << 3)) return;
    const int i = blockIdx.y * 256 + threadIdx.x;
    if (threadIdx.x < 32) jb[threadIdx.x] = g_props[wcol * 32 + threadIdx.x];
    __syncthreads();
    if (i >= PRE_NMS) return;
    float4 a = g_props[i];
    float areaA = (a.z - a.x) * (a.w - a.y);
    unsigned m = 0;
#pragma unroll 4
    for (int k = 0; k < 32; ++k) {
        float4 b = jb[k];
        float areaB = (b.z - b.x) * (b.w - b.y);
        float lx = fmaxf(a.x, b.x), ly = fmaxf(a.y, b.y);
        float rx = fminf(a.z, b.z), ry = fminf(a.w, b.w);
        float iw = fmaxf(rx - lx, 0.f), ih = fmaxf(ry - ly, 0.f);
        float inter = iw * ih;
        float iou = __fdiv_rn(inter, areaA + areaB - inter + 1e-9f);
        if (iou > 0.7f) m |= (1u << k);
    }
    g_mask[i * NWORDS + wcol] = m;
}

// ---------------- 6: single-warp NMS reduce with POST_NMS early exit ---------
__global__ void __launch_bounds__(32) nmsred_k() {
    const int t = threadIdx.x;
    unsigned remv[6];
#pragma unroll
    for (int j = 0; j < 6; ++j) {
        int w = j * 32 + t;
        remv[j] = (w < NWORDS) ? g_invalid[w] : 0u;
    }
    unsigned row[8][6];
#pragma unroll
    for (int r = 0; r < 8; ++r)
#pragma unroll
        for (int j = 0; j < 6; ++j) {
            int w = j * 32 + t;
            row[r][j] = (w < NWORDS) ? g_mask[r * NWORDS + w] : 0u;
        }
    int cnt = 0;
#pragma unroll
    for (int slot = 0; slot < 6; ++slot) {
        const int iend = (slot + 1) * 1024 < PRE_NMS ? (slot + 1) * 1024 : PRE_NMS;
        for (int ib = slot * 1024; ib < iend; ib += 8) {
#pragma unroll
            for (int r = 0; r < 8; ++r) {
                const int i = ib + r;
                const int wi = i >> 5;
                const int owner = wi & 31;
                unsigned b = (remv[slot] >> (i & 31)) & 1u;
                unsigned sup = __shfl_sync(0xFFFFFFFFu, b, owner);
                int kp = !sup;
                if (t == 0) g_keep[i] = kp;
                cnt += kp;
                if (kp) {
#pragma unroll
                    for (int j = 0; j < 6; ++j) remv[j] |= row[r][j];
                }
                if (cnt >= POST_NMS) return;
                const int ni = i + 8;
                if (ni < PRE_NMS) {
#pragma unroll
                    for (int j = 0; j < 6; ++j) {
                        int w = j * 32 + t;
                        row[r][j] = (w < NWORDS) ? g_mask[ni * NWORDS + w] : 0u;
                    }
                }
            }
        }
    }
}

// ---------------- 7: compact kept boxes into output --------------------------
__global__ void __launch_bounds__(256) out_k(float* __restrict__ out) {
    __shared__ int pre[256];
    const int t = threadIdx.x;
    const int base = t * 24;
    int s = 0;
    for (int k = 0; k < 24; ++k) {
        int i = base + k;
        if (i < PRE_NMS && g_keep[i]) s++;
    }
    pre[t] = s;
    __syncthreads();
    for (int off = 1; off < 256; off <<= 1) {
        int v = (t >= off) ? pre[t - off] : 0;
        __syncthreads();
        pre[t] += v;
        __syncthreads();
    }
    int rank = pre[t] - s;                  // exclusive prefix
    for (int k = 0; k < 24; ++k) {
        int i = base + k;
        if (i < PRE_NMS && g_keep[i]) {
            if (rank < POST_NMS) {
                float4 b = g_props[i];
                out[rank * 4 + 0] = b.x;
                out[rank * 4 + 1] = b.y;
                out[rank * 4 + 2] = b.z;
                out[rank * 4 + 3] = b.w;
            }
            rank++;
        }
    }
}

// ---------------- launcher ---------------------------------------------------
extern "C" void kernel_launch(void* const* d_in, const int* in_sizes, int n_in,
                              void* d_out, int out_size) {
    const float* feature = (const float*)d_in[0];
    const float* w1   = (const float*)d_in[1];
    const float* b1   = (const float*)d_in[2];
    const float* wcls = (const float*)d_in[3];
    const float* bcls = (const float*)d_in[4];
    const float* wreg = (const float*)d_in[5];
    const float* breg = (const float*)d_in[6];
    const int*   imh  = (const int*)d_in[7];
    const int*   imw  = (const int*)d_in[8];
    float* out = (float*)d_out;

    cudaFuncSetAttribute(sortdec_k, cudaFuncAttributeMaxDynamicSharedMemorySize,
                         CAND_CAP * 8);

    init_k<<<2304, 256>>>(w1, out);
    conv3x3_k<<<900, 256>>>(feature, b1);
    heads_k<<<(NPIX + 255) / 256, 256>>>(wcls, bcls, wreg, breg);
    scan1_k<<<1, 256>>>();
    hist2_k<<<(NANCH + 255) / 256, 256>>>();
    scan2_k<<<1, 256>>>();
    compact_k<<<(NANCH + 255) / 256, 256>>>();
    sortdec_k<<<1, 1024, CAND_CAP * 8>>>(imh, imw);
    iou_k<<<dim3(NWORDS, (PRE_NMS + 255) / 256), 256>>>();
    nmsred_k<<<1, 32>>>();
    out_k<<<1, 256>>>(out);
}

// round 9
// speedup vs baseline: 2.7701x; 1.3425x over previous
#include <cuda_runtime.h>
#include <cuda_bf16.h>
#include <cstdint>

#define HH 200
#define WW 272
#define NPIX 54400
#define NANCH 489600
#define PRE_NMS 6000
#define SELCAP 7500
#define NWORDS 188
#define NBOX_PAD 6016
#define POST_NMS 1000
#define CAND_CAP 8192
#define NPIXW 1700

#define PADW 274
#define PADH 202
#define NPAD (PADH * PADW)        // 55348
#define FGUARD 416
#define FROWS (NPAD + 2 * FGUARD) // 56180
#define KTOT 2304
#define NITER 36
#define GN 433

typedef unsigned long long ull;

// ---------------- scratch ----------------------------------------------------
__device__ float        g_x[256 * NPIX];          // APPROX conv output (fp32)
__device__ float        g_wt[2304 * 256];         // exact fp32 weights, transposed
__device__ __align__(16) __nv_bfloat16 g_F0[FROWS * 256];  // bf16 padded NHWC feat
__device__ __align__(16) __nv_bfloat16 g_A[256 * KTOT];    // bf16 weights [oc][K]
__device__ unsigned     g_key[NANCH];             // approx keys; exact for cand px
__device__ float4       g_off4[NANCH];            // exact offsets (cand px only)
__device__ float        g_xr[CAND_CAP * 256];     // exact conv cols per cand px
__device__ int          g_hist[65536];
__device__ int          g_hist2[65536];
__device__ int          g_B, g_need;
__device__ unsigned     g_T;
__device__ int          g_cnt, g_npix;
__device__ int          g_canda[CAND_CAP];
__device__ unsigned     g_pixmask[NPIXW];
__device__ int          g_plist[CAND_CAP];
__device__ unsigned long long g_cand[CAND_CAP];
__device__ float4       g_props[NBOX_PAD];
__device__ unsigned     g_invalid[NWORDS];
__device__ unsigned     g_mask[PRE_NMS * NWORDS];
__device__ int          g_keep[PRE_NMS];

__device__ __constant__ float c_aw[9] = {
    45.254833995939045f, 32.f, 22.627416997969522f,
    90.50966799187809f,  64.f, 45.254833995939045f,
    181.01933598375618f, 128.f, 90.50966799187809f};
__device__ __constant__ float c_ah[9] = {
    22.627416997969522f, 32.f, 45.254833995939045f,
    45.254833995939045f, 64.f, 90.50966799187809f,
    90.50966799187809f,  128.f, 181.01933598375618f};

__device__ __forceinline__ unsigned fkey(float f) {
    unsigned u = __float_as_uint(f);
    return (u & 0x80000000u) ? ~u : (u | 0x80000000u);
}

// ---------------- PTX helpers -------------------------------------------------
__device__ __forceinline__ uint32_t smem_u32(const void* p) {
    uint32_t a;
    asm("{ .reg .u64 t; cvta.to.shared.u64 t, %1; cvt.u32.u64 %0, t; }"
        : "=r"(a) : "l"(p));
    return a;
}
#define SW128(o) ((o) ^ (((o) >> 3) & 0x70))
__device__ __forceinline__ void cpa16(uint32_t s, const void* g) {
    asm volatile("cp.async.cg.shared.global [%0], [%1], 16;" ::"r"(s), "l"(g));
}
__device__ __forceinline__ void ldsm4(unsigned* r, uint32_t a) {
    asm volatile(
        "ldmatrix.sync.aligned.m8n8.x4.shared.b16 {%0,%1,%2,%3}, [%4];"
        : "=r"(r[0]), "=r"(r[1]), "=r"(r[2]), "=r"(r[3]) : "r"(a));
}
__device__ __forceinline__ void mma16816(float* c, const unsigned* a,
                                         const unsigned* b) {
    asm volatile(
        "mma.sync.aligned.m16n8k16.row.col.f32.bf16.bf16.f32 "
        "{%0,%1,%2,%3}, {%4,%5,%6,%7}, {%8,%9}, {%0,%1,%2,%3};"
        : "+f"(c[0]), "+f"(c[1]), "+f"(c[2]), "+f"(c[3])
        : "r"(a[0]), "r"(a[1]), "r"(a[2]), "r"(a[3]), "r"(b[0]), "r"(b[1]));
}

// ---------------- 0: init -----------------------------------------------------
__global__ void init_k(const float* __restrict__ w1, float* __restrict__ out) {
    int i = blockIdx.x * 256 + threadIdx.x;
    if (i < 256 * 2304) {
        int oc = i / 2304, r = i % 2304;       // r = ic*9 + tap
        float v = w1[i];
        g_wt[r * 256 + oc] = v;
        int ic = r / 9, tap = r % 9;
        g_A[oc * KTOT + tap * 256 + ic] = __float2bfloat16(v);
    }
    if (i < 65536) { g_hist[i] = 0; g_hist2[i] = 0; }
    if (i < PRE_NMS) g_keep[i] = 0;
    if (i < NPIXW) g_pixmask[i] = 0;
    if (i == 0) { g_cnt = 0; g_npix = 0; }
    if (i < NWORDS) g_invalid[i] = 0;
    if (i < POST_NMS * 4) out[i] = 0.f;
}

// ---------------- 0b: zero padded bf16 feature --------------------------------
__global__ void zf_k() {
    const long long per = (long long)FROWS * 256 / 8;
    long long i = (long long)blockIdx.x * 256 + threadIdx.x;
    if (i < per) ((uint4*)g_F0)[i] = make_uint4(0, 0, 0, 0);
}

// ---------------- 1: feature prep: NCHW fp32 -> padded NHWC bf16 --------------
__global__ void __launch_bounds__(256) fprep_k(const float* __restrict__ f) {
    __shared__ float s[32][257];
    const int tid = threadIdx.x;
    const int p0 = blockIdx.x * 32;
    for (int l = tid; l < 32 * 256; l += 256) {
        int ic = l >> 5, j = l & 31;
        int p = p0 + j;
        s[j][ic] = (p < NPIX) ? f[ic * NPIX + p] : 0.f;
    }
    __syncthreads();
    for (int l = tid; l < 32 * 256; l += 256) {
        int j = l >> 8, ic = l & 255;
        int p = p0 + j;
        if (p >= NPIX) continue;
        int y = p / WW, x = p % WW;
        long long n = (long long)(FGUARD + (y + 1) * PADW + (x + 1)) * 256 + ic;
        g_F0[n] = __float2bfloat16(s[j][ic]);
    }
}

// ---------------- 2: APPROX conv via HMMA bf16 implicit GEMM ------------------
// grid (433, 2), block 256 (8 warps: 4 m x 2 n). Tile 128 oc x 128 px, K=2304.
__global__ void __launch_bounds__(256) gemm_k(const float* __restrict__ b1) {
    extern __shared__ __align__(16) char dsm_raw[];
    char* smem = (char*)(((uintptr_t)dsm_raw + 1023) & ~(uintptr_t)1023);
    const int tid = threadIdx.x;
    const int lane = tid & 31;
    const int wm = (tid >> 5) & 3;
    const int wn = tid >> 7;
    const int n0 = blockIdx.x * 128;
    const int m0 = blockIdx.y * 128;
    const uint32_t sbase = smem_u32(smem);

    float acc[2][8][4];
#pragma unroll
    for (int mt = 0; mt < 2; ++mt)
#pragma unroll
        for (int nt = 0; nt < 8; ++nt)
#pragma unroll
            for (int q = 0; q < 4; ++q) acc[mt][nt][q] = 0.f;

    auto load_chunk = [&](int c) {
        const int k   = c >> 2;              // tap 0..8
        const int icb = c & 3;
        const int offk = (k / 3 - 1) * PADW + (k % 3 - 1);
        const uint32_t bufA = sbase + (c & 1) * 32768;
        const uint32_t bufB = bufA + 16384;
#pragma unroll
        for (int j = 0; j < 4; ++j) {
            int o = tid * 4 + j;
            int row = o >> 3, seg = o & 7;
            cpa16(bufA + SW128(row * 128 + seg * 16),
                  g_A + (long long)(m0 + row) * KTOT + c * 64 + seg * 8);
            cpa16(bufB + SW128(row * 128 + seg * 16),
                  g_F0 + (long long)(FGUARD + n0 + offk + row) * 256 + icb * 64 +
                      seg * 8);
        }
        asm volatile("cp.async.commit_group;" ::: "memory");
    };

    load_chunk(0);
#pragma unroll 1
    for (int c = 0; c < NITER; ++c) {
        if (c + 1 < NITER) {
            load_chunk(c + 1);
            asm volatile("cp.async.wait_group 1;" ::: "memory");
        } else {
            asm volatile("cp.async.wait_group 0;" ::: "memory");
        }
        __syncthreads();

        const uint32_t bufA = sbase + (c & 1) * 32768;
        const uint32_t bufB = bufA + 16384;
#pragma unroll
        for (int ks = 0; ks < 4; ++ks) {
            const int kb = ks * 32;
            unsigned af[2][4], bf[8][2];
#pragma unroll
            for (int mt = 0; mt < 2; ++mt) {
                int row = wm * 32 + mt * 16 + (lane & 15);
                ldsm4(af[mt],
                      bufA + SW128(row * 128 + kb + ((lane >> 4) << 4)));
            }
#pragma unroll
            for (int nt2 = 0; nt2 < 4; ++nt2) {
                int row = wn * 64 + nt2 * 16 + (lane & 7) +
                          ((lane & 16) ? 8 : 0);
                unsigned t4[4];
                ldsm4(t4, bufB + SW128(row * 128 + kb +
                                       ((lane & 8) ? 16 : 0)));
                bf[nt2 * 2][0] = t4[0];
                bf[nt2 * 2][1] = t4[1];
                bf[nt2 * 2 + 1][0] = t4[2];
                bf[nt2 * 2 + 1][1] = t4[3];
            }
#pragma unroll
            for (int mt = 0; mt < 2; ++mt)
#pragma unroll
                for (int nt = 0; nt < 8; ++nt)
                    mma16816(acc[mt][nt], af[mt], bf[nt]);
        }
        __syncthreads();
    }

    float bias[2][2];
#pragma unroll
    for (int mt = 0; mt < 2; ++mt) {
        int r = m0 + wm * 32 + mt * 16 + (lane >> 2);
        bias[mt][0] = b1[r];
        bias[mt][1] = b1[r + 8];
    }
#pragma unroll
    for (int nt = 0; nt < 8; ++nt) {
        int ncol = n0 + wn * 64 + nt * 8 + 2 * (lane & 3);
        int py0 = ncol / PADW, px0 = ncol % PADW;
        int py1 = (ncol + 1) / PADW, px1 = (ncol + 1) % PADW;
        bool v0 = (ncol < NPAD) && py0 >= 1 && py0 <= HH && px0 >= 1 && px0 <= WW;
        bool v1 = (ncol + 1 < NPAD) && py1 >= 1 && py1 <= HH && px1 >= 1 && px1 <= WW;
        long long o0 = (long long)(py0 - 1) * WW + (px0 - 1);
        long long o1 = (long long)(py1 - 1) * WW + (px1 - 1);
#pragma unroll
        for (int mt = 0; mt < 2; ++mt) {
            int oc_lo = m0 + wm * 32 + mt * 16 + (lane >> 2);
            int oc_hi = oc_lo + 8;
            if (v0) g_x[(long long)oc_lo * NPIX + o0] =
                fmaxf(acc[mt][nt][0] + bias[mt][0], 0.f);
            if (v1) g_x[(long long)oc_lo * NPIX + o1] =
                fmaxf(acc[mt][nt][1] + bias[mt][0], 0.f);
            if (v0) g_x[(long long)oc_hi * NPIX + o0] =
                fmaxf(acc[mt][nt][2] + bias[mt][1], 0.f);
            if (v1) g_x[(long long)oc_hi * NPIX + o1] =
                fmaxf(acc[mt][nt][3] + bias[mt][1], 0.f);
        }
    }
}

// ---------------- 3: APPROX cls head -> approx keys + histogram ---------------
__global__ void __launch_bounds__(256) headsA_k(const float* __restrict__ wcls,
                                                const float* __restrict__ bcls) {
    __shared__ float4 swc[9 * 64];
    const int t = threadIdx.x;
    for (int l = t; l < 9 * 64; l += 256) swc[l] = ((const float4*)wcls)[l];
    __syncthreads();
    const int p = blockIdx.x * 256 + t;
    if (p >= NPIX) return;
    float c0[9];
#pragma unroll
    for (int a = 0; a < 9; ++a) c0[a] = bcls[a];
    for (int icq = 0; icq < 64; ++icq) {
        const int ic = icq * 4;
        float xa0 = g_x[ic * NPIX + p];
        float xa1 = g_x[(ic + 1) * NPIX + p];
        float xa2 = g_x[(ic + 2) * NPIX + p];
        float xa3 = g_x[(ic + 3) * NPIX + p];
#pragma unroll
        for (int a = 0; a < 9; ++a) {
            float4 w = swc[a * 64 + icq];
            c0[a] += xa0 * w.x + xa1 * w.y;
            c0[a] += xa2 * w.z + xa3 * w.w;
        }
    }
#pragma unroll
    for (int a = 0; a < 9; ++a) {
        unsigned k = fkey(c0[a]);
        g_key[p * 9 + a] = k;
        atomicAdd(&g_hist[k >> 16], 1);
    }
}

// ---------------- 4: approx threshold for top-SELCAP --------------------------
__global__ void scan1_k() {
    __shared__ int suf1[256];
    __shared__ int suf2[256];
    __shared__ int s_tc, s_b;
    const int t = threadIdx.x;
    int s = 0;
    const int4* hp = (const int4*)&g_hist[t * 256];
#pragma unroll 8
    for (int k = 0; k < 64; ++k) { int4 v = hp[k]; s += v.x + v.y + v.z + v.w; }
    if (t == 0) { s_tc = -1; s_b = -1; }
    suf1[t] = s;
    __syncthreads();
    for (int off = 1; off < 256; off <<= 1) {
        int v = (t + off < 256) ? suf1[t + off] : 0;
        __syncthreads();
        suf1[t] += v;
        __syncthreads();
    }
    if (suf1[t] >= SELCAP) atomicMax(&s_tc, t);
    __syncthreads();
    const int tc = s_tc;
    const int S1 = (tc + 1 < 256) ? suf1[tc + 1] : 0;
    suf2[t] = g_hist[tc * 256 + t];
    __syncthreads();
    for (int off = 1; off < 256; off <<= 1) {
        int v = (t + off < 256) ? suf2[t + off] : 0;
        __syncthreads();
        suf2[t] += v;
        __syncthreads();
    }
    if (S1 + suf2[t] >= SELCAP) atomicMax(&s_b, t);
    __syncthreads();
    if (t == 0) {
        int b = s_b;
        int S = S1 + ((b + 1 < 256) ? suf2[b + 1] : 0);
        g_B = tc * 256 + b;
        g_need = SELCAP - S;
    }
}

__global__ void hist2_k() {
    int i = blockIdx.x * 256 + threadIdx.x;
    if (i < NANCH) {
        unsigned k = g_key[i];
        if ((int)(k >> 16) == g_B) atomicAdd(&g_hist2[k & 0xFFFFu], 1);
    }
}

__global__ void scan2_k() {
    __shared__ int suf1[256];
    __shared__ int suf2[256];
    __shared__ int s_tc, s_b;
    const int t = threadIdx.x;
    const int need = g_need;
    int s = 0;
    const int4* hp = (const int4*)&g_hist2[t * 256];
#pragma unroll 8
    for (int k = 0; k < 64; ++k) { int4 v = hp[k]; s += v.x + v.y + v.z + v.w; }
    if (t == 0) { s_tc = -1; s_b = -1; }
    suf1[t] = s;
    __syncthreads();
    for (int off = 1; off < 256; off <<= 1) {
        int v = (t + off < 256) ? suf1[t + off] : 0;
        __syncthreads();
        suf1[t] += v;
        __syncthreads();
    }
    if (suf1[t] >= need) atomicMax(&s_tc, t);
    __syncthreads();
    const int tc = s_tc;
    const int S1 = (tc + 1 < 256) ? suf1[tc + 1] : 0;
    suf2[t] = g_hist2[tc * 256 + t];
    __syncthreads();
    for (int off = 1; off < 256; off <<= 1) {
        int v = (t + off < 256) ? suf2[t + off] : 0;
        __syncthreads();
        suf2[t] += v;
        __syncthreads();
    }
    if (S1 + suf2[t] >= need) atomicMax(&s_b, t);
    __syncthreads();
    if (t == 0) {
        int L = tc * 256 + s_b;
        g_T = ((unsigned)g_B << 16) | (unsigned)L;
    }
}

// ---------------- 5: compact candidate anchors + mark pixels ------------------
__global__ void compactA_k() {
    int i = blockIdx.x * 256 + threadIdx.x;
    if (i < NANCH) {
        unsigned k = g_key[i];
        if (k >= g_T) {
            int pos = atomicAdd(&g_cnt, 1);
            if (pos < CAND_CAP) {
                g_canda[pos] = i;
                int p = i / 9;
                atomicOr(&g_pixmask[p >> 5], 1u << (p & 31));
            }
        }
    }
}

// ---------------- 6: compact candidate pixel list -----------------------------
__global__ void pixcomp_k() {
    int w = blockIdx.x * 256 + threadIdx.x;
    if (w >= NPIXW) return;
    unsigned bits = g_pixmask[w];
    int n = __popc(bits);
    if (n == 0) return;
    int pos = atomicAdd(&g_npix, n);
    while (bits) {
        int b = __ffs(bits) - 1;
        bits &= bits - 1;
        g_plist[pos++] = w * 32 + b;
    }
}

// ---------------- 7: EXACT per-pixel conv rescore -----------------------------
// Per-output FMA chain is (icb, ic, tap) ascending with fmaf — identical
// rounding sequence to the previously-passing conv realization.
__global__ void __launch_bounds__(256) rescore_k(const float* __restrict__ f,
                                                 const float* __restrict__ b1) {
    __shared__ float sw[8][9][128];
    __shared__ float sx[16][73];
    __shared__ int spx[16];
    const int npix = g_npix;
    const int pg = blockIdx.x;
    if (pg * 16 >= npix) return;
    const int oc0 = blockIdx.y * 128;
    const int t = threadIdx.x;
    const int px = t & 15, og = t >> 4;
    if (t < 16) {
        int slot = pg * 16 + t;
        spx[t] = (slot < npix) ? g_plist[slot] : -1;
    }
    __syncthreads();
    const int myp = spx[px];

    float acc[8];
#pragma unroll
    for (int j = 0; j < 8; ++j) acc[j] = 0.f;

    for (int icb = 0; icb < 32; ++icb) {
        const int ic0 = icb * 8;
        for (int l = t; l < 16 * 72; l += 256) {
            int pxi = l / 72, r = l % 72;
            int ic = r / 9, tap = r % 9;
            int ky = tap / 3, kx = tap % 3;
            int p = spx[pxi];
            float v = 0.f;
            if (p >= 0) {
                int y = p / WW, x = p % WW;
                int gy = y + ky - 1, gx = x + kx - 1;
                if (gy >= 0 && gy < HH && gx >= 0 && gx < WW)
                    v = f[(ic0 + ic) * NPIX + gy * WW + gx];
            }
            sx[pxi][r] = v;
        }
        for (int l = t; l < 8 * 9 * 128; l += 256) {
            int oc = l & 127;
            int rk = l >> 7;
            int ic = rk / 9, k = rk % 9;
            sw[ic][k][oc] = g_wt[((ic0 + ic) * 9 + k) * 256 + oc0 + oc];
        }
        __syncthreads();
#pragma unroll 2
        for (int ic = 0; ic < 8; ++ic) {
#pragma unroll
            for (int tap = 0; tap < 9; ++tap) {
                float xv = sx[px][ic * 9 + tap];
                const float4* wp = (const float4*)&sw[ic][tap][og * 8];
                float4 w0 = wp[0], w1 = wp[1];
                acc[0] = fmaf(xv, w0.x, acc[0]);
                acc[1] = fmaf(xv, w0.y, acc[1]);
                acc[2] = fmaf(xv, w0.z, acc[2]);
                acc[3] = fmaf(xv, w0.w, acc[3]);
                acc[4] = fmaf(xv, w1.x, acc[4]);
                acc[5] = fmaf(xv, w1.y, acc[5]);
                acc[6] = fmaf(xv, w1.z, acc[6]);
                acc[7] = fmaf(xv, w1.w, acc[7]);
            }
        }
        __syncthreads();
    }
    if (myp >= 0) {
        int slot = pg * 16 + px;
#pragma unroll
        for (int j = 0; j < 8; ++j) {
            int oc = oc0 + og * 8 + j;
            g_xr[slot * 256 + oc] = fmaxf(acc[j] + b1[oc], 0.f);
        }
    }
}

// ---------------- 8: EXACT heads on candidate pixels --------------------------
// Identical source expressions to the previously-passing heads realization.
__global__ void __launch_bounds__(256) headsE_k(const float* __restrict__ wcls,
                                                const float* __restrict__ bcls,
                                                const float* __restrict__ wreg,
                                                const float* __restrict__ breg) {
    __shared__ float4 swc[9 * 64];
    __shared__ float4 swr[36 * 64];
    const int t = threadIdx.x;
    for (int l = t; l < 9 * 64; l += 256)  swc[l] = ((const float4*)wcls)[l];
    for (int l = t; l < 36 * 64; l += 256) swr[l] = ((const float4*)wreg)[l];
    __syncthreads();
    const int slot = blockIdx.x * 256 + t;
    if (slot >= g_npix) return;
    const int p = g_plist[slot];
    const float* xr = &g_xr[slot * 256];

    float c0[9], r0[36];
#pragma unroll
    for (int a = 0; a < 9; ++a)  c0[a] = bcls[a];
#pragma unroll
    for (int o = 0; o < 36; ++o) r0[o] = breg[o];

    for (int icq = 0; icq < 64; ++icq) {
        const int ic = icq * 4;
        float xa0 = xr[ic];
        float xa1 = xr[ic + 1];
        float xa2 = xr[ic + 2];
        float xa3 = xr[ic + 3];
#pragma unroll
        for (int a = 0; a < 9; ++a) {
            float4 w = swc[a * 64 + icq];
            c0[a] += xa0 * w.x + xa1 * w.y;
            c0[a] += xa2 * w.z + xa3 * w.w;
        }
#pragma unroll
        for (int o = 0; o < 36; ++o) {
            float4 w = swr[o * 64 + icq];
            r0[o] += xa0 * w.x + xa1 * w.y;
            r0[o] += xa2 * w.z + xa3 * w.w;
        }
    }
#pragma unroll
    for (int a = 0; a < 9; ++a) {
        int n = p * 9 + a;
        g_key[n] = fkey(c0[a]);                  // exact overwrite
        g_off4[n] = make_float4(r0[4 * a], r0[4 * a + 1], r0[4 * a + 2],
                                r0[4 * a + 3]);
    }
}

// ---------------- 9: build exact sort records ---------------------------------
__global__ void candfix_k() {
    int i = blockIdx.x * 256 + threadIdx.x;
    int cnt = g_cnt;
    if (cnt > CAND_CAP) cnt = CAND_CAP;
    if (i < cnt) {
        int a = g_canda[i];
        g_cand[i] = ((unsigned long long)g_key[a] << 32) |
                    (unsigned long long)(0xFFFFFFFFu - (unsigned)a);
    }
}

// ---------------- 10: bitonic sort + fused decode -----------------------------
__global__ void __launch_bounds__(1024) sortdec_k(const int* __restrict__ imh,
                                                  const int* __restrict__ imw) {
    extern __shared__ unsigned long long s[];
    int t = threadIdx.x;
    int cnt = g_cnt;
    if (cnt > CAND_CAP) cnt = CAND_CAP;
    for (int l = t; l < CAND_CAP; l += 1024)
        s[l] = (l < cnt) ? g_cand[l] : 0ULL;
    __syncthreads();
    for (int k = 2; k <= CAND_CAP; k <<= 1) {
        for (int j = k >> 1; j > 0; j >>= 1) {
            for (int idx = t; idx < CAND_CAP; idx += 1024) {
                int ixj = idx ^ j;
                if (ixj > idx) {
                    unsigned long long va = s[idx], vb = s[ixj];
                    bool up = ((idx & k) == 0);
                    if (up ? (va < vb) : (va > vb)) { s[idx] = vb; s[ixj] = va; }
                }
            }
            __syncthreads();
        }
    }
    const float W = (float)imw[0], H = (float)imh[0];
    for (int i = t; i < NBOX_PAD; i += 1024) {
        if (i >= PRE_NMS) { g_props[i] = make_float4(0.f, 0.f, 0.f, 0.f); continue; }
        int n = (int)(0xFFFFFFFFu - (unsigned)s[i]);
        int a = n % 9, p = n / 9;
        int x = p % WW, y = p / WW;
        float cx0 = (x + 0.5f) * 4.f, cy0 = (y + 0.5f) * 4.f;
        float x1a = cx0 - 0.5f * c_aw[a], x2a = cx0 + 0.5f * c_aw[a];
        float y1a = cy0 - 0.5f * c_ah[a], y2a = cy0 + 0.5f * c_ah[a];
        float wa = x2a - x1a, ha = y2a - y1a;
        float cxa = x1a + 0.5f * wa, cya = y1a + 0.5f * ha;
        float4 d = g_off4[n];
        float cx = d.x * wa + cxa, cy = d.y * ha + cya;
        float w = expf(d.z) * wa, h = expf(d.w) * ha;
        float x1 = fminf(fmaxf(cx - 0.5f * w, 0.f), W);
        float y1 = fminf(fmaxf(cy - 0.5f * h, 0.f), H);
        float x2 = fminf(fmaxf(cx + 0.5f * w, 0.f), W);
        float y2 = fminf(fmaxf(cy + 0.5f * h, 0.f), H);
        g_props[i] = make_float4(x1, y1, x2, y2);
        bool valid = ((x2 - x1) >= 1.f) && ((y2 - y1) >= 1.f);
        if (!valid) atomicOr(&g_invalid[i >> 5], 1u << (i & 31));
    }
}

// ---------------- 11: IoU bitmask (upper triangle) ----------------------------
__global__ void __launch_bounds__(256) iou_k() {
    __shared__ float4 jb[32];
    const int wcol = blockIdx.x;
    if (wcol < (int)(blockIdx.y << 3)) return;
    const int i = blockIdx.y * 256 + threadIdx.x;
    if (threadIdx.x < 32) jb[threadIdx.x] = g_props[wcol * 32 + threadIdx.x];
    __syncthreads();
    if (i >= PRE_NMS) return;
    float4 a = g_props[i];
    float areaA = (a.z - a.x) * (a.w - a.y);
    unsigned m = 0;
#pragma unroll 4
    for (int k = 0; k < 32; ++k) {
        float4 b = jb[k];
        float areaB = (b.z - b.x) * (b.w - b.y);
        float lx = fmaxf(a.x, b.x), ly = fmaxf(a.y, b.y);
        float rx = fminf(a.z, b.z), ry = fminf(a.w, b.w);
        float iw = fmaxf(rx - lx, 0.f), ih = fmaxf(ry - ly, 0.f);
        float inter = iw * ih;
        float iou = __fdiv_rn(inter, areaA + areaB - inter + 1e-9f);
        if (iou > 0.7f) m |= (1u << k);
    }
    g_mask[i * NWORDS + wcol] = m;
}

// ---------------- 12: single-warp NMS reduce (POST_NMS early exit) ------------
__global__ void __launch_bounds__(32) nmsred_k() {
    const int t = threadIdx.x;
    unsigned remv[6];
#pragma unroll
    for (int j = 0; j < 6; ++j) {
        int w = j * 32 + t;
        remv[j] = (w < NWORDS) ? g_invalid[w] : 0u;
    }
    unsigned row[8][6];
#pragma unroll
    for (int r = 0; r < 8; ++r)
#pragma unroll
        for (int j = 0; j < 6; ++j) {
            int w = j * 32 + t;
            row[r][j] = (w < NWORDS) ? g_mask[r * NWORDS + w] : 0u;
        }
    int cnt = 0;
#pragma unroll
    for (int slot = 0; slot < 6; ++slot) {
        const int iend = (slot + 1) * 1024 < PRE_NMS ? (slot + 1) * 1024 : PRE_NMS;
        for (int ib = slot * 1024; ib < iend; ib += 8) {
#pragma unroll
            for (int r = 0; r < 8; ++r) {
                const int i = ib + r;
                const int wi = i >> 5;
                const int owner = wi & 31;
                unsigned b = (remv[slot] >> (i & 31)) & 1u;
                unsigned sup = __shfl_sync(0xFFFFFFFFu, b, owner);
                int kp = !sup;
                if (t == 0) g_keep[i] = kp;
                cnt += kp;
                if (kp) {
#pragma unroll
                    for (int j = 0; j < 6; ++j) remv[j] |= row[r][j];
                }
                if (cnt >= POST_NMS) return;
                const int ni = i + 8;
                if (ni < PRE_NMS) {
#pragma unroll
                    for (int j = 0; j < 6; ++j) {
                        int w = j * 32 + t;
                        row[r][j] = (w < NWORDS) ? g_mask[ni * NWORDS + w] : 0u;
                    }
                }
            }
        }
    }
}

// ---------------- 13: compact kept boxes into output --------------------------
__global__ void __launch_bounds__(256) out_k(float* __restrict__ out) {
    __shared__ int pre[256];
    const int t = threadIdx.x;
    const int base = t * 24;
    int s = 0;
    for (int k = 0; k < 24; ++k) {
        int i = base + k;
        if (i < PRE_NMS && g_keep[i]) s++;
    }
    pre[t] = s;
    __syncthreads();
    for (int off = 1; off < 256; off <<= 1) {
        int v = (t >= off) ? pre[t - off] : 0;
        __syncthreads();
        pre[t] += v;
        __syncthreads();
    }
    int rank = pre[t] - s;
    for (int k = 0; k < 24; ++k) {
        int i = base + k;
        if (i < PRE_NMS && g_keep[i]) {
            if (rank < POST_NMS) {
                float4 b = g_props[i];
                out[rank * 4 + 0] = b.x;
                out[rank * 4 + 1] = b.y;
                out[rank * 4 + 2] = b.z;
                out[rank * 4 + 3] = b.w;
            }
            rank++;
        }
    }
}

// ---------------- launcher ----------------------------------------------------
extern "C" void kernel_launch(void* const* d_in, const int* in_sizes, int n_in,
                              void* d_out, int out_size) {
    const float* feature = (const float*)d_in[0];
    const float* w1   = (const float*)d_in[1];
    const float* b1   = (const float*)d_in[2];
    const float* wcls = (const float*)d_in[3];
    const float* bcls = (const float*)d_in[4];
    const float* wreg = (const float*)d_in[5];
    const float* breg = (const float*)d_in[6];
    const int*   imh  = (const int*)d_in[7];
    const int*   imw  = (const int*)d_in[8];
    float* out = (float*)d_out;

    static int inited = 0;
    if (!inited) {
        cudaFuncSetAttribute(sortdec_k,
                             cudaFuncAttributeMaxDynamicSharedMemorySize,
                             CAND_CAP * 8);
        cudaFuncSetAttribute(gemm_k,
                             cudaFuncAttributeMaxDynamicSharedMemorySize, 66560);
        inited = 1;
    }

    const long long zf_total = (long long)FROWS * 256 / 8;
    init_k<<<2304, 256>>>(w1, out);
    zf_k<<<(unsigned)((zf_total + 255) / 256), 256>>>();
    fprep_k<<<(NPIX + 31) / 32, 256>>>(feature);
    gemm_k<<<dim3(GN, 2), 256, 66560>>>(b1);
    headsA_k<<<(NPIX + 255) / 256, 256>>>(wcls, bcls);
    scan1_k<<<1, 256>>>();
    hist2_k<<<(NANCH + 255) / 256, 256>>>();
    scan2_k<<<1, 256>>>();
    compactA_k<<<(NANCH + 255) / 256, 256>>>();
    pixcomp_k<<<(NPIXW + 255) / 256, 256>>>();
    rescore_k<<<dim3(512, 2), 256>>>(feature, b1);
    headsE_k<<<CAND_CAP / 256, 256>>>(wcls, bcls, wreg, breg);
    candfix_k<<<CAND_CAP / 256, 256>>>();
    sortdec_k<<<1, 1024, CAND_CAP * 8>>>(imh, imw);
    iou_k<<<dim3(NWORDS, (PRE_NMS + 255) / 256), 256>>>();
    nmsred_k<<<1, 32>>>();
    out_k<<<1, 256>>>(out);
}

// round 10
// speedup vs baseline: 3.0644x; 1.1062x over previous
#include <cuda_runtime.h>
#include <cuda_bf16.h>
#include <cstdint>

#define HH 200
#define WW 272
#define NPIX 54400
#define NANCH 489600
#define PRE_NMS 6000
#define SELCAP 7500
#define NWORDS 188
#define NBOX_PAD 6016
#define POST_NMS 1000
#define CAND_CAP 8192
#define NPIXW 1700

#define PADW 274
#define PADH 202
#define NPAD (PADH * PADW)        // 55348
#define FGUARD 416
#define FROWS (NPAD + 2 * FGUARD) // 56180
#define KTOT 2304
#define NITER 36
#define GN 433

typedef unsigned long long ull;

// ---------------- scratch ----------------------------------------------------
__device__ __nv_bfloat16 g_xh[256 * NPIX];        // APPROX conv output (bf16)
__device__ float        g_wt[2304 * 256];         // exact fp32 weights, transposed
__device__ __align__(16) __nv_bfloat16 g_F0[FROWS * 256];  // bf16 padded NHWC feat
__device__ __align__(16) __nv_bfloat16 g_A[256 * KTOT];    // bf16 weights [oc][K]
__device__ unsigned     g_key[NANCH];             // approx keys; exact for cand px
__device__ float4       g_off4[NANCH];            // exact offsets (cand px only)
__device__ float        g_xr[CAND_CAP * 256];     // exact conv cols per cand px
__device__ int          g_hist[65536];
__device__ int          g_hist2[65536];
__device__ int          g_B, g_need;
__device__ unsigned     g_T;
__device__ int          g_cnt, g_npix;
__device__ int          g_canda[CAND_CAP];
__device__ unsigned     g_pixmask[NPIXW];
__device__ int          g_plist[CAND_CAP];
__device__ unsigned long long g_cand[CAND_CAP];
__device__ float4       g_props[NBOX_PAD];
__device__ unsigned     g_invalid[NWORDS];
__device__ unsigned     g_mask[PRE_NMS * NWORDS];
__device__ int          g_keep[PRE_NMS];

__device__ __constant__ float c_aw[9] = {
    45.254833995939045f, 32.f, 22.627416997969522f,
    90.50966799187809f,  64.f, 45.254833995939045f,
    181.01933598375618f, 128.f, 90.50966799187809f};
__device__ __constant__ float c_ah[9] = {
    22.627416997969522f, 32.f, 45.254833995939045f,
    45.254833995939045f, 64.f, 90.50966799187809f,
    90.50966799187809f,  128.f, 181.01933598375618f};

__device__ __forceinline__ unsigned fkey(float f) {
    unsigned u = __float_as_uint(f);
    return (u & 0x80000000u) ? ~u : (u | 0x80000000u);
}

// ---------------- PTX helpers -------------------------------------------------
__device__ __forceinline__ uint32_t smem_u32(const void* p) {
    uint32_t a;
    asm("{ .reg .u64 t; cvta.to.shared.u64 t, %1; cvt.u32.u64 %0, t; }"
        : "=r"(a) : "l"(p));
    return a;
}
#define SW128(o) ((o) ^ (((o) >> 3) & 0x70))
__device__ __forceinline__ void cpa16(uint32_t s, const void* g) {
    asm volatile("cp.async.cg.shared.global [%0], [%1], 16;" ::"r"(s), "l"(g));
}
__device__ __forceinline__ void ldsm4(unsigned* r, uint32_t a) {
    asm volatile(
        "ldmatrix.sync.aligned.m8n8.x4.shared.b16 {%0,%1,%2,%3}, [%4];"
        : "=r"(r[0]), "=r"(r[1]), "=r"(r[2]), "=r"(r[3]) : "r"(a));
}
__device__ __forceinline__ void mma16816(float* c, const unsigned* a,
                                         const unsigned* b) {
    asm volatile(
        "mma.sync.aligned.m16n8k16.row.col.f32.bf16.bf16.f32 "
        "{%0,%1,%2,%3}, {%4,%5,%6,%7}, {%8,%9}, {%0,%1,%2,%3};"
        : "+f"(c[0]), "+f"(c[1]), "+f"(c[2]), "+f"(c[3])
        : "r"(a[0]), "r"(a[1]), "r"(a[2]), "r"(a[3]), "r"(b[0]), "r"(b[1]));
}

// ---------------- 0: init -----------------------------------------------------
__global__ void init_k(const float* __restrict__ w1, float* __restrict__ out) {
    int i = blockIdx.x * 256 + threadIdx.x;
    if (i < 256 * 2304) {
        int oc = i / 2304, r = i % 2304;       // r = ic*9 + tap
        float v = w1[i];
        g_wt[r * 256 + oc] = v;
        int ic = r / 9, tap = r % 9;
        g_A[oc * KTOT + tap * 256 + ic] = __float2bfloat16(v);
    }
    if (i < 65536) { g_hist[i] = 0; g_hist2[i] = 0; }
    if (i < PRE_NMS) g_keep[i] = 0;
    if (i < NPIXW) g_pixmask[i] = 0;
    if (i == 0) { g_cnt = 0; g_npix = 0; }
    if (i < NWORDS) g_invalid[i] = 0;
    if (i < POST_NMS * 4) out[i] = 0.f;
}

// ---------------- 0b: zero padded bf16 feature --------------------------------
__global__ void zf_k() {
    const long long per = (long long)FROWS * 256 / 8;
    long long i = (long long)blockIdx.x * 256 + threadIdx.x;
    if (i < per) ((uint4*)g_F0)[i] = make_uint4(0, 0, 0, 0);
}

// ---------------- 1: feature prep: NCHW fp32 -> padded NHWC bf16 --------------
__global__ void __launch_bounds__(256) fprep_k(const float* __restrict__ f) {
    __shared__ float s[32][257];
    const int tid = threadIdx.x;
    const int p0 = blockIdx.x * 32;
    for (int l = tid; l < 32 * 256; l += 256) {
        int ic = l >> 5, j = l & 31;
        int p = p0 + j;
        s[j][ic] = (p < NPIX) ? f[ic * NPIX + p] : 0.f;
    }
    __syncthreads();
    for (int l = tid; l < 32 * 256; l += 256) {
        int j = l >> 8, ic = l & 255;
        int p = p0 + j;
        if (p >= NPIX) continue;
        int y = p / WW, x = p % WW;
        long long n = (long long)(FGUARD + (y + 1) * PADW + (x + 1)) * 256 + ic;
        g_F0[n] = __float2bfloat16(s[j][ic]);
    }
}

// ---------------- 2: APPROX conv via HMMA bf16 (3-stage cp.async) -------------
// grid (433, 2), block 256 (8 warps: 4 m x 2 n). Tile 128 oc x 128 px, K=2304.
__global__ void __launch_bounds__(256) gemm_k(const float* __restrict__ b1) {
    extern __shared__ __align__(16) char dsm_raw[];
    char* smem = (char*)(((uintptr_t)dsm_raw + 1023) & ~(uintptr_t)1023);
    const int tid = threadIdx.x;
    const int lane = tid & 31;
    const int wm = (tid >> 5) & 3;
    const int wn = tid >> 7;
    const int n0 = blockIdx.x * 128;
    const int m0 = blockIdx.y * 128;
    const uint32_t sbase = smem_u32(smem);

    float acc[2][8][4];
#pragma unroll
    for (int mt = 0; mt < 2; ++mt)
#pragma unroll
        for (int nt = 0; nt < 8; ++nt)
#pragma unroll
            for (int q = 0; q < 4; ++q) acc[mt][nt][q] = 0.f;

    auto load_chunk = [&](int c) {
        const int k   = c >> 2;              // tap 0..8
        const int icb = c & 3;
        const int offk = (k / 3 - 1) * PADW + (k % 3 - 1);
        const uint32_t bufA = sbase + (c % 3) * 32768;
        const uint32_t bufB = bufA + 16384;
#pragma unroll
        for (int j = 0; j < 4; ++j) {
            int o = tid * 4 + j;
            int row = o >> 3, seg = o & 7;
            cpa16(bufA + SW128(row * 128 + seg * 16),
                  g_A + (long long)(m0 + row) * KTOT + c * 64 + seg * 8);
            cpa16(bufB + SW128(row * 128 + seg * 16),
                  g_F0 + (long long)(FGUARD + n0 + offk + row) * 256 + icb * 64 +
                      seg * 8);
        }
        asm volatile("cp.async.commit_group;" ::: "memory");
    };

    load_chunk(0);
    load_chunk(1);
#pragma unroll 1
    for (int c = 0; c < NITER; ++c) {
        if (c + 2 < NITER) load_chunk(c + 2);
        else asm volatile("cp.async.commit_group;" ::: "memory");
        asm volatile("cp.async.wait_group 2;" ::: "memory");
        __syncthreads();

        const uint32_t bufA = sbase + (c % 3) * 32768;
        const uint32_t bufB = bufA + 16384;
#pragma unroll
        for (int ks = 0; ks < 4; ++ks) {
            const int kb = ks * 32;
            unsigned af[2][4], bf[8][2];
#pragma unroll
            for (int mt = 0; mt < 2; ++mt) {
                int row = wm * 32 + mt * 16 + (lane & 15);
                ldsm4(af[mt],
                      bufA + SW128(row * 128 + kb + ((lane >> 4) << 4)));
            }
#pragma unroll
            for (int nt2 = 0; nt2 < 4; ++nt2) {
                int row = wn * 64 + nt2 * 16 + (lane & 7) +
                          ((lane & 16) ? 8 : 0);
                unsigned t4[4];
                ldsm4(t4, bufB + SW128(row * 128 + kb +
                                       ((lane & 8) ? 16 : 0)));
                bf[nt2 * 2][0] = t4[0];
                bf[nt2 * 2][1] = t4[1];
                bf[nt2 * 2 + 1][0] = t4[2];
                bf[nt2 * 2 + 1][1] = t4[3];
            }
#pragma unroll
            for (int mt = 0; mt < 2; ++mt)
#pragma unroll
                for (int nt = 0; nt < 8; ++nt)
                    mma16816(acc[mt][nt], af[mt], bf[nt]);
        }
        __syncthreads();
    }

    float bias[2][2];
#pragma unroll
    for (int mt = 0; mt < 2; ++mt) {
        int r = m0 + wm * 32 + mt * 16 + (lane >> 2);
        bias[mt][0] = b1[r];
        bias[mt][1] = b1[r + 8];
    }
#pragma unroll
    for (int nt = 0; nt < 8; ++nt) {
        int ncol = n0 + wn * 64 + nt * 8 + 2 * (lane & 3);
        int py0 = ncol / PADW, px0 = ncol % PADW;
        int py1 = (ncol + 1) / PADW, px1 = (ncol + 1) % PADW;
        bool v0 = (ncol < NPAD) && py0 >= 1 && py0 <= HH && px0 >= 1 && px0 <= WW;
        bool v1 = (ncol + 1 < NPAD) && py1 >= 1 && py1 <= HH && px1 >= 1 && px1 <= WW;
        long long o0 = (long long)(py0 - 1) * WW + (px0 - 1);
        long long o1 = (long long)(py1 - 1) * WW + (px1 - 1);
#pragma unroll
        for (int mt = 0; mt < 2; ++mt) {
            int oc_lo = m0 + wm * 32 + mt * 16 + (lane >> 2);
            int oc_hi = oc_lo + 8;
            if (v0) g_xh[(long long)oc_lo * NPIX + o0] =
                __float2bfloat16(fmaxf(acc[mt][nt][0] + bias[mt][0], 0.f));
            if (v1) g_xh[(long long)oc_lo * NPIX + o1] =
                __float2bfloat16(fmaxf(acc[mt][nt][1] + bias[mt][0], 0.f));
            if (v0) g_xh[(long long)oc_hi * NPIX + o0] =
                __float2bfloat16(fmaxf(acc[mt][nt][2] + bias[mt][1], 0.f));
            if (v1) g_xh[(long long)oc_hi * NPIX + o1] =
                __float2bfloat16(fmaxf(acc[mt][nt][3] + bias[mt][1], 0.f));
        }
    }
}

// ---------------- 3: APPROX cls head (bf16x2, 2 px/thread) --------------------
__global__ void __launch_bounds__(256) headsA_k(const float* __restrict__ wcls,
                                                const float* __restrict__ bcls) {
    __shared__ float4 swc[9 * 64];
    const int t = threadIdx.x;
    for (int l = t; l < 9 * 64; l += 256) swc[l] = ((const float4*)wcls)[l];
    __syncthreads();
    const int p2 = blockIdx.x * 256 + t;
    if (p2 >= NPIX / 2) return;
    const int p0 = p2 * 2;
    float c0[9], c1[9];
#pragma unroll
    for (int a = 0; a < 9; ++a) { c0[a] = bcls[a]; c1[a] = bcls[a]; }
    for (int icq = 0; icq < 64; ++icq) {
        const int ic = icq * 4;
        float2 x0 = __bfloat1622float2(
            *(const __nv_bfloat162*)&g_xh[ic * NPIX + p0]);
        float2 x1 = __bfloat1622float2(
            *(const __nv_bfloat162*)&g_xh[(ic + 1) * NPIX + p0]);
        float2 x2 = __bfloat1622float2(
            *(const __nv_bfloat162*)&g_xh[(ic + 2) * NPIX + p0]);
        float2 x3 = __bfloat1622float2(
            *(const __nv_bfloat162*)&g_xh[(ic + 3) * NPIX + p0]);
#pragma unroll
        for (int a = 0; a < 9; ++a) {
            float4 w = swc[a * 64 + icq];
            c0[a] += x0.x * w.x + x1.x * w.y;
            c0[a] += x2.x * w.z + x3.x * w.w;
            c1[a] += x0.y * w.x + x1.y * w.y;
            c1[a] += x2.y * w.z + x3.y * w.w;
        }
    }
#pragma unroll
    for (int a = 0; a < 9; ++a) {
        unsigned k = fkey(c0[a]);
        g_key[p0 * 9 + a] = k;
        atomicAdd(&g_hist[k >> 16], 1);
        unsigned k1 = fkey(c1[a]);
        g_key[(p0 + 1) * 9 + a] = k1;
        atomicAdd(&g_hist[k1 >> 16], 1);
    }
}

// ---------------- 4: approx threshold for top-SELCAP --------------------------
__global__ void scan1_k() {
    __shared__ int suf1[256];
    __shared__ int suf2[256];
    __shared__ int s_tc, s_b;
    const int t = threadIdx.x;
    int s = 0;
    const int4* hp = (const int4*)&g_hist[t * 256];
#pragma unroll 8
    for (int k = 0; k < 64; ++k) { int4 v = hp[k]; s += v.x + v.y + v.z + v.w; }
    if (t == 0) { s_tc = -1; s_b = -1; }
    suf1[t] = s;
    __syncthreads();
    for (int off = 1; off < 256; off <<= 1) {
        int v = (t + off < 256) ? suf1[t + off] : 0;
        __syncthreads();
        suf1[t] += v;
        __syncthreads();
    }
    if (suf1[t] >= SELCAP) atomicMax(&s_tc, t);
    __syncthreads();
    const int tc = s_tc;
    const int S1 = (tc + 1 < 256) ? suf1[tc + 1] : 0;
    suf2[t] = g_hist[tc * 256 + t];
    __syncthreads();
    for (int off = 1; off < 256; off <<= 1) {
        int v = (t + off < 256) ? suf2[t + off] : 0;
        __syncthreads();
        suf2[t] += v;
        __syncthreads();
    }
    if (S1 + suf2[t] >= SELCAP) atomicMax(&s_b, t);
    __syncthreads();
    if (t == 0) {
        int b = s_b;
        int S = S1 + ((b + 1 < 256) ? suf2[b + 1] : 0);
        g_B = tc * 256 + b;
        g_need = SELCAP - S;
    }
}

__global__ void hist2_k() {
    int i = blockIdx.x * 256 + threadIdx.x;
    if (i < NANCH) {
        unsigned k = g_key[i];
        if ((int)(k >> 16) == g_B) atomicAdd(&g_hist2[k & 0xFFFFu], 1);
    }
}

__global__ void scan2_k() {
    __shared__ int suf1[256];
    __shared__ int suf2[256];
    __shared__ int s_tc, s_b;
    const int t = threadIdx.x;
    const int need = g_need;
    int s = 0;
    const int4* hp = (const int4*)&g_hist2[t * 256];
#pragma unroll 8
    for (int k = 0; k < 64; ++k) { int4 v = hp[k]; s += v.x + v.y + v.z + v.w; }
    if (t == 0) { s_tc = -1; s_b = -1; }
    suf1[t] = s;
    __syncthreads();
    for (int off = 1; off < 256; off <<= 1) {
        int v = (t + off < 256) ? suf1[t + off] : 0;
        __syncthreads();
        suf1[t] += v;
        __syncthreads();
    }
    if (suf1[t] >= need) atomicMax(&s_tc, t);
    __syncthreads();
    const int tc = s_tc;
    const int S1 = (tc + 1 < 256) ? suf1[tc + 1] : 0;
    suf2[t] = g_hist2[tc * 256 + t];
    __syncthreads();
    for (int off = 1; off < 256; off <<= 1) {
        int v = (t + off < 256) ? suf2[t + off] : 0;
        __syncthreads();
        suf2[t] += v;
        __syncthreads();
    }
    if (S1 + suf2[t] >= need) atomicMax(&s_b, t);
    __syncthreads();
    if (t == 0) {
        int L = tc * 256 + s_b;
        g_T = ((unsigned)g_B << 16) | (unsigned)L;
    }
}

// ---------------- 5: compact candidate anchors + mark pixels ------------------
__global__ void compactA_k() {
    int i = blockIdx.x * 256 + threadIdx.x;
    if (i < NANCH) {
        unsigned k = g_key[i];
        if (k >= g_T) {
            int pos = atomicAdd(&g_cnt, 1);
            if (pos < CAND_CAP) {
                g_canda[pos] = i;
                int p = i / 9;
                atomicOr(&g_pixmask[p >> 5], 1u << (p & 31));
            }
        }
    }
}

// ---------------- 6: compact candidate pixel list -----------------------------
__global__ void pixcomp_k() {
    int w = blockIdx.x * 256 + threadIdx.x;
    if (w >= NPIXW) return;
    unsigned bits = g_pixmask[w];
    int n = __popc(bits);
    if (n == 0) return;
    int pos = atomicAdd(&g_npix, n);
    while (bits) {
        int b = __ffs(bits) - 1;
        bits &= bits - 1;
        g_plist[pos++] = w * 32 + b;
    }
}

// ---------------- 7: EXACT per-pixel conv rescore (32 px/block) ---------------
// Per-output FMA chain is (icb, ic, tap) ascending with fmaf — identical
// rounding sequence to the previously-passing conv realization.
__global__ void __launch_bounds__(256) rescore_k(const float* __restrict__ f,
                                                 const float* __restrict__ b1) {
    __shared__ float sw[8][9][128];
    __shared__ float sx[32][73];
    __shared__ int spx[32];
    const int npix = g_npix;
    const int pg = blockIdx.x;
    if (pg * 32 >= npix) return;
    const int oc0 = blockIdx.y * 128;
    const int t = threadIdx.x;
    const int px = t & 31, og = t >> 5;       // 8 oc-groups of 16 oc
    if (t < 32) {
        int slot = pg * 32 + t;
        spx[t] = (slot < npix) ? g_plist[slot] : -1;
    }
    __syncthreads();
    const int myp = spx[px];

    float acc[16];
#pragma unroll
    for (int j = 0; j < 16; ++j) acc[j] = 0.f;

    for (int icb = 0; icb < 32; ++icb) {
        const int ic0 = icb * 8;
        for (int l = t; l < 32 * 72; l += 256) {
            int pxi = l / 72, r = l % 72;
            int ic = r / 9, tap = r % 9;
            int ky = tap / 3, kx = tap % 3;
            int p = spx[pxi];
            float v = 0.f;
            if (p >= 0) {
                int y = p / WW, x = p % WW;
                int gy = y + ky - 1, gx = x + kx - 1;
                if (gy >= 0 && gy < HH && gx >= 0 && gx < WW)
                    v = f[(ic0 + ic) * NPIX + gy * WW + gx];
            }
            sx[pxi][r] = v;
        }
        for (int l = t; l < 8 * 9 * 128; l += 256) {
            int oc = l & 127;
            int rk = l >> 7;
            int ic = rk / 9, k = rk % 9;
            sw[ic][k][oc] = g_wt[((ic0 + ic) * 9 + k) * 256 + oc0 + oc];
        }
        __syncthreads();
#pragma unroll 2
        for (int ic = 0; ic < 8; ++ic) {
#pragma unroll
            for (int tap = 0; tap < 9; ++tap) {
                float xv = sx[px][ic * 9 + tap];
                const float4* wp = (const float4*)&sw[ic][tap][og * 16];
                float4 w0 = wp[0], w1 = wp[1], w2 = wp[2], w3 = wp[3];
                acc[0]  = fmaf(xv, w0.x, acc[0]);
                acc[1]  = fmaf(xv, w0.y, acc[1]);
                acc[2]  = fmaf(xv, w0.z, acc[2]);
                acc[3]  = fmaf(xv, w0.w, acc[3]);
                acc[4]  = fmaf(xv, w1.x, acc[4]);
                acc[5]  = fmaf(xv, w1.y, acc[5]);
                acc[6]  = fmaf(xv, w1.z, acc[6]);
                acc[7]  = fmaf(xv, w1.w, acc[7]);
                acc[8]  = fmaf(xv, w2.x, acc[8]);
                acc[9]  = fmaf(xv, w2.y, acc[9]);
                acc[10] = fmaf(xv, w2.z, acc[10]);
                acc[11] = fmaf(xv, w2.w, acc[11]);
                acc[12] = fmaf(xv, w3.x, acc[12]);
                acc[13] = fmaf(xv, w3.y, acc[13]);
                acc[14] = fmaf(xv, w3.z, acc[14]);
                acc[15] = fmaf(xv, w3.w, acc[15]);
            }
        }
        __syncthreads();
    }
    if (myp >= 0) {
        int slot = pg * 32 + px;
#pragma unroll
        for (int j = 0; j < 16; ++j) {
            int oc = oc0 + og * 16 + j;
            g_xr[slot * 256 + oc] = fmaxf(acc[j] + b1[oc], 0.f);
        }
    }
}

// ---------------- 8: EXACT heads on candidate pixels --------------------------
__global__ void __launch_bounds__(256) headsE_k(const float* __restrict__ wcls,
                                                const float* __restrict__ bcls,
                                                const float* __restrict__ wreg,
                                                const float* __restrict__ breg) {
    __shared__ float4 swc[9 * 64];
    __shared__ float4 swr[36 * 64];
    const int t = threadIdx.x;
    for (int l = t; l < 9 * 64; l += 256)  swc[l] = ((const float4*)wcls)[l];
    for (int l = t; l < 36 * 64; l += 256) swr[l] = ((const float4*)wreg)[l];
    __syncthreads();
    const int slot = blockIdx.x * 256 + t;
    if (slot >= g_npix) return;
    const int p = g_plist[slot];
    const float* xr = &g_xr[slot * 256];

    float c0[9], r0[36];
#pragma unroll
    for (int a = 0; a < 9; ++a)  c0[a] = bcls[a];
#pragma unroll
    for (int o = 0; o < 36; ++o) r0[o] = breg[o];

    for (int icq = 0; icq < 64; ++icq) {
        const int ic = icq * 4;
        float xa0 = xr[ic];
        float xa1 = xr[ic + 1];
        float xa2 = xr[ic + 2];
        float xa3 = xr[ic + 3];
#pragma unroll
        for (int a = 0; a < 9; ++a) {
            float4 w = swc[a * 64 + icq];
            c0[a] += xa0 * w.x + xa1 * w.y;
            c0[a] += xa2 * w.z + xa3 * w.w;
        }
#pragma unroll
        for (int o = 0; o < 36; ++o) {
            float4 w = swr[o * 64 + icq];
            r0[o] += xa0 * w.x + xa1 * w.y;
            r0[o] += xa2 * w.z + xa3 * w.w;
        }
    }
#pragma unroll
    for (int a = 0; a < 9; ++a) {
        int n = p * 9 + a;
        g_key[n] = fkey(c0[a]);                  // exact overwrite
        g_off4[n] = make_float4(r0[4 * a], r0[4 * a + 1], r0[4 * a + 2],
                                r0[4 * a + 3]);
    }
}

// ---------------- 9: build exact sort records ---------------------------------
__global__ void candfix_k() {
    int i = blockIdx.x * 256 + threadIdx.x;
    int cnt = g_cnt;
    if (cnt > CAND_CAP) cnt = CAND_CAP;
    if (i < cnt) {
        int a = g_canda[i];
        g_cand[i] = ((unsigned long long)g_key[a] << 32) |
                    (unsigned long long)(0xFFFFFFFFu - (unsigned)a);
    }
}

// ---------------- 10: bitonic sort + fused decode -----------------------------
__global__ void __launch_bounds__(1024) sortdec_k(const int* __restrict__ imh,
                                                  const int* __restrict__ imw) {
    extern __shared__ unsigned long long s[];
    int t = threadIdx.x;
    int cnt = g_cnt;
    if (cnt > CAND_CAP) cnt = CAND_CAP;
    for (int l = t; l < CAND_CAP; l += 1024)
        s[l] = (l < cnt) ? g_cand[l] : 0ULL;
    __syncthreads();
    for (int k = 2; k <= CAND_CAP; k <<= 1) {
        for (int j = k >> 1; j > 0; j >>= 1) {
            for (int idx = t; idx < CAND_CAP; idx += 1024) {
                int ixj = idx ^ j;
                if (ixj > idx) {
                    unsigned long long va = s[idx], vb = s[ixj];
                    bool up = ((idx & k) == 0);
                    if (up ? (va < vb) : (va > vb)) { s[idx] = vb; s[ixj] = va; }
                }
            }
            __syncthreads();
        }
    }
    const float W = (float)imw[0], H = (float)imh[0];
    for (int i = t; i < NBOX_PAD; i += 1024) {
        if (i >= PRE_NMS) { g_props[i] = make_float4(0.f, 0.f, 0.f, 0.f); continue; }
        int n = (int)(0xFFFFFFFFu - (unsigned)s[i]);
        int a = n % 9, p = n / 9;
        int x = p % WW, y = p / WW;
        float cx0 = (x + 0.5f) * 4.f, cy0 = (y + 0.5f) * 4.f;
        float x1a = cx0 - 0.5f * c_aw[a], x2a = cx0 + 0.5f * c_aw[a];
        float y1a = cy0 - 0.5f * c_ah[a], y2a = cy0 + 0.5f * c_ah[a];
        float wa = x2a - x1a, ha = y2a - y1a;
        float cxa = x1a + 0.5f * wa, cya = y1a + 0.5f * ha;
        float4 d = g_off4[n];
        float cx = d.x * wa + cxa, cy = d.y * ha + cya;
        float w = expf(d.z) * wa, h = expf(d.w) * ha;
        float x1 = fminf(fmaxf(cx - 0.5f * w, 0.f), W);
        float y1 = fminf(fmaxf(cy - 0.5f * h, 0.f), H);
        float x2 = fminf(fmaxf(cx + 0.5f * w, 0.f), W);
        float y2 = fminf(fmaxf(cy + 0.5f * h, 0.f), H);
        g_props[i] = make_float4(x1, y1, x2, y2);
        bool valid = ((x2 - x1) >= 1.f) && ((y2 - y1) >= 1.f);
        if (!valid) atomicOr(&g_invalid[i >> 5], 1u << (i & 31));
    }
}

// ---------------- 11: IoU bitmask (upper triangle) ----------------------------
__global__ void __launch_bounds__(256) iou_k() {
    __shared__ float4 jb[32];
    const int wcol = blockIdx.x;
    if (wcol < (int)(blockIdx.y << 3)) return;
    const int i = blockIdx.y * 256 + threadIdx.x;
    if (threadIdx.x < 32) jb[threadIdx.x] = g_props[wcol * 32 + threadIdx.x];
    __syncthreads();
    if (i >= PRE_NMS) return;
    float4 a = g_props[i];
    float areaA = (a.z - a.x) * (a.w - a.y);
    unsigned m = 0;
#pragma unroll 4
    for (int k = 0; k < 32; ++k) {
        float4 b = jb[k];
        float areaB = (b.z - b.x) * (b.w - b.y);
        float lx = fmaxf(a.x, b.x), ly = fmaxf(a.y, b.y);
        float rx = fminf(a.z, b.z), ry = fminf(a.w, b.w);
        float iw = fmaxf(rx - lx, 0.f), ih = fmaxf(ry - ly, 0.f);
        float inter = iw * ih;
        float iou = __fdiv_rn(inter, areaA + areaB - inter + 1e-9f);
        if (iou > 0.7f) m |= (1u << k);
    }
    g_mask[i * NWORDS + wcol] = m;
}

// ---------------- 12: single-warp NMS reduce (POST_NMS early exit) ------------
__global__ void __launch_bounds__(32) nmsred_k() {
    const int t = threadIdx.x;
    unsigned remv[6];
#pragma unroll
    for (int j = 0; j < 6; ++j) {
        int w = j * 32 + t;
        remv[j] = (w < NWORDS) ? g_invalid[w] : 0u;
    }
    unsigned row[8][6];
#pragma unroll
    for (int r = 0; r < 8; ++r)
#pragma unroll
        for (int j = 0; j < 6; ++j) {
            int w = j * 32 + t;
            row[r][j] = (w < NWORDS) ? g_mask[r * NWORDS + w] : 0u;
        }
    int cnt = 0;
#pragma unroll
    for (int slot = 0; slot < 6; ++slot) {
        const int iend = (slot + 1) * 1024 < PRE_NMS ? (slot + 1) * 1024 : PRE_NMS;
        for (int ib = slot * 1024; ib < iend; ib += 8) {
#pragma unroll
            for (int r = 0; r < 8; ++r) {
                const int i = ib + r;
                const int wi = i >> 5;
                const int owner = wi & 31;
                unsigned b = (remv[slot] >> (i & 31)) & 1u;
                unsigned sup = __shfl_sync(0xFFFFFFFFu, b, owner);
                int kp = !sup;
                if (t == 0) g_keep[i] = kp;
                cnt += kp;
                if (kp) {
#pragma unroll
                    for (int j = 0; j < 6; ++j) remv[j] |= row[r][j];
                }
                if (cnt >= POST_NMS) return;
                const int ni = i + 8;
                if (ni < PRE_NMS) {
#pragma unroll
                    for (int j = 0; j < 6; ++j) {
                        int w = j * 32 + t;
                        row[r][j] = (w < NWORDS) ? g_mask[ni * NWORDS + w] : 0u;
                    }
                }
            }
        }
    }
}

// ---------------- 13: compact kept boxes into output --------------------------
__global__ void __launch_bounds__(256) out_k(float* __restrict__ out) {
    __shared__ int pre[256];
    const int t = threadIdx.x;
    const int base = t * 24;
    int s = 0;
    for (int k = 0; k < 24; ++k) {
        int i = base + k;
        if (i < PRE_NMS && g_keep[i]) s++;
    }
    pre[t] = s;
    __syncthreads();
    for (int off = 1; off < 256; off <<= 1) {
        int v = (t >= off) ? pre[t - off] : 0;
        __syncthreads();
        pre[t] += v;
        __syncthreads();
    }
    int rank = pre[t] - s;
    for (int k = 0; k < 24; ++k) {
        int i = base + k;
        if (i < PRE_NMS && g_keep[i]) {
            if (rank < POST_NMS) {
                float4 b = g_props[i];
                out[rank * 4 + 0] = b.x;
                out[rank * 4 + 1] = b.y;
                out[rank * 4 + 2] = b.z;
                out[rank * 4 + 3] = b.w;
            }
            rank++;
        }
    }
}

// ---------------- launcher ----------------------------------------------------
extern "C" void kernel_launch(void* const* d_in, const int* in_sizes, int n_in,
                              void* d_out, int out_size) {
    const float* feature = (const float*)d_in[0];
    const float* w1   = (const float*)d_in[1];
    const float* b1   = (const float*)d_in[2];
    const float* wcls = (const float*)d_in[3];
    const float* bcls = (const float*)d_in[4];
    const float* wreg = (const float*)d_in[5];
    const float* breg = (const float*)d_in[6];
    const int*   imh  = (const int*)d_in[7];
    const int*   imw  = (const int*)d_in[8];
    float* out = (float*)d_out;

    static int inited = 0;
    if (!inited) {
        cudaFuncSetAttribute(sortdec_k,
                             cudaFuncAttributeMaxDynamicSharedMemorySize,
                             CAND_CAP * 8);
        cudaFuncSetAttribute(gemm_k,
                             cudaFuncAttributeMaxDynamicSharedMemorySize, 99328);
        inited = 1;
    }

    const long long zf_total = (long long)FROWS * 256 / 8;
    init_k<<<2304, 256>>>(w1, out);
    zf_k<<<(unsigned)((zf_total + 255) / 256), 256>>>();
    fprep_k<<<(NPIX + 31) / 32, 256>>>(feature);
    gemm_k<<<dim3(GN, 2), 256, 99328>>>(b1);
    headsA_k<<<(NPIX / 2 + 255) / 256, 256>>>(wcls, bcls);
    scan1_k<<<1, 256>>>();
    hist2_k<<<(NANCH + 255) / 256, 256>>>();
    scan2_k<<<1, 256>>>();
    compactA_k<<<(NANCH + 255) / 256, 256>>>();
    pixcomp_k<<<(NPIXW + 255) / 256, 256>>>();
    rescore_k<<<dim3(256, 2), 256>>>(feature, b1);
    headsE_k<<<CAND_CAP / 256, 256>>>(wcls, bcls, wreg, breg);
    candfix_k<<<CAND_CAP / 256, 256>>>();
    sortdec_k<<<1, 1024, CAND_CAP * 8>>>(imh, imw);
    iou_k<<<dim3(NWORDS, (PRE_NMS + 255) / 256), 256>>>();
    nmsred_k<<<1, 32>>>();
    out_k<<<1, 256>>>(out);
}